// round 1
// baseline (speedup 1.0000x reference)
#include <cuda_runtime.h>
#include <cuda_bf16.h>

// Problem constants
#define BB 2
#define LL 2048
#define DIM 2048
#define NH 16
#define NKV 8
#define HD 128
#define WIN 128
#define NREP (NH / NKV)
#define MROWS (BB * LL)   // 4096

// Scratch (allocation-free rule: __device__ globals)
__device__ float g_q[(size_t)MROWS * NH * HD];     // 32 MB
__device__ float g_k[(size_t)MROWS * NKV * HD];    // 16 MB
__device__ float g_v[(size_t)MROWS * NKV * HD];    // 16 MB
__device__ float g_attn[(size_t)MROWS * NH * HD];  // 32 MB

// ---------------------------------------------------------------------------
// SGEMM: C[m, n] = sum_k A[m,k] * Bw[n,k]   (A: MxK row-major, Bw: NxK row-major)
// All dims multiples of tile sizes (no bounds checks).
// BM=BN=128, BK=16, TM=TN=8, 256 threads.
// ---------------------------------------------------------------------------
template <int BM, int BN, int BK, int TM, int TN>
__global__ __launch_bounds__(256, 2)
void sgemm_abt(const float* __restrict__ A, const float* __restrict__ Bw,
               float* __restrict__ C, int K, int ldc)
{
    __shared__ float As[BK][BM];
    __shared__ float Bs[BK][BN];

    const int block_row = blockIdx.y * BM;
    const int block_col = blockIdx.x * BN;
    const int tid = threadIdx.x;

    const int tcol = (tid % (BN / TN)) * TN;   // 0..120
    const int trow = (tid / (BN / TN)) * TM;   // 0..120

    float acc[TM][TN];
#pragma unroll
    for (int i = 0; i < TM; ++i)
#pragma unroll
        for (int j = 0; j < TN; ++j) acc[i][j] = 0.0f;

    for (int kt = 0; kt < K; kt += BK) {
        // Load A tile (BM x BK) -> As[BK][BM] (transposed)
#pragma unroll
        for (int i = 0; i < (BM * BK) / (256 * 4); ++i) {
            int v = tid + i * 256;
            int r = v / (BK / 4);
            int c = (v % (BK / 4)) * 4;
            float4 t = *(const float4*)(A + (size_t)(block_row + r) * K + kt + c);
            As[c + 0][r] = t.x; As[c + 1][r] = t.y;
            As[c + 2][r] = t.z; As[c + 3][r] = t.w;
        }
        // Load B tile (BN x BK) -> Bs[BK][BN] (transposed)
#pragma unroll
        for (int i = 0; i < (BN * BK) / (256 * 4); ++i) {
            int v = tid + i * 256;
            int r = v / (BK / 4);
            int c = (v % (BK / 4)) * 4;
            float4 t = *(const float4*)(Bw + (size_t)(block_col + r) * K + kt + c);
            Bs[c + 0][r] = t.x; Bs[c + 1][r] = t.y;
            Bs[c + 2][r] = t.z; Bs[c + 3][r] = t.w;
        }
        __syncthreads();

#pragma unroll
        for (int kk = 0; kk < BK; ++kk) {
            float ra[TM], rb[TN];
            float4 a0 = *(const float4*)&As[kk][trow];
            float4 a1 = *(const float4*)&As[kk][trow + 4];
            ra[0] = a0.x; ra[1] = a0.y; ra[2] = a0.z; ra[3] = a0.w;
            ra[4] = a1.x; ra[5] = a1.y; ra[6] = a1.z; ra[7] = a1.w;
            float4 b0 = *(const float4*)&Bs[kk][tcol];
            float4 b1 = *(const float4*)&Bs[kk][tcol + 4];
            rb[0] = b0.x; rb[1] = b0.y; rb[2] = b0.z; rb[3] = b0.w;
            rb[4] = b1.x; rb[5] = b1.y; rb[6] = b1.z; rb[7] = b1.w;
#pragma unroll
            for (int i = 0; i < TM; ++i)
#pragma unroll
                for (int j = 0; j < TN; ++j)
                    acc[i][j] += ra[i] * rb[j];
        }
        __syncthreads();
    }

#pragma unroll
    for (int i = 0; i < TM; ++i) {
#pragma unroll
        for (int j = 0; j < TN; j += 4) {
            float4 t = make_float4(acc[i][j], acc[i][j + 1], acc[i][j + 2], acc[i][j + 3]);
            *(float4*)(C + (size_t)(block_row + trow + i) * ldc + block_col + tcol + j) = t;
        }
    }
}

// ---------------------------------------------------------------------------
// RoPE (HF rotate_half) applied in-place to g_q and g_k.
// One thread per (row, head, d<64) pair.
// ---------------------------------------------------------------------------
__global__ void rope_kernel(const float* __restrict__ cosp, const float* __restrict__ sinp)
{
    int idx = blockIdx.x * blockDim.x + threadIdx.x;
    const int total = MROWS * (NH + NKV) * (HD / 2);
    if (idx >= total) return;

    int d = idx & 63;
    int rest = idx >> 6;
    int hh = rest % (NH + NKV);
    int row = rest / (NH + NKV);
    int l = row & (LL - 1);

    float c1 = cosp[l * HD + d];
    float s1 = sinp[l * HD + d];
    float c2 = cosp[l * HD + d + 64];
    float s2 = sinp[l * HD + d + 64];

    float* base;
    if (hh < NH) base = g_q + ((size_t)row * NH + hh) * HD;
    else         base = g_k + ((size_t)row * NKV + (hh - NH)) * HD;

    float t1 = base[d];
    float t2 = base[d + 64];
    base[d]      = t1 * c1 - t2 * s1;   // d < 64: rot = -t2
    base[d + 64] = t2 * c2 + t1 * s2;   // d >= 64: rot = +t1
}

// ---------------------------------------------------------------------------
// Sliding-window causal attention. One warp per query; 8 adjacent queries of
// the same (b,h) per block so the K/V window stays hot in L1.
// Keys j in [max(0, i-WIN), i]  (<= 129 keys).
// ---------------------------------------------------------------------------
__global__ __launch_bounds__(256)
void attn_kernel()
{
    const int lane = threadIdx.x & 31;
    const int w = threadIdx.x >> 5;
    const int bid = blockIdx.x;

    const int lt = bid % (LL / 8);
    const int bh = bid / (LL / 8);
    const int h = bh % NH;
    const int b = bh / NH;
    const int i = lt * 8 + w;            // query position
    const int kh = h / NREP;

    __shared__ float sc[8][136];

    const float* qp = g_q + (((size_t)(b * LL + i)) * NH + h) * HD;
    float q0 = qp[lane], q1 = qp[lane + 32], q2 = qp[lane + 64], q3 = qp[lane + 96];

    const int s = (i - WIN > 0) ? (i - WIN) : 0;
    const int cnt = i - s + 1;
    const float scale = 0.08838834764831845f;  // 128^-0.5

    float mx = -1e30f;
    const float* kbase = g_k + (((size_t)(b * LL + s)) * NKV + kh) * HD;
    for (int j = 0; j < cnt; ++j) {
        const float* kp = kbase + (size_t)j * (NKV * HD);
        float d = q0 * kp[lane] + q1 * kp[lane + 32] + q2 * kp[lane + 64] + q3 * kp[lane + 96];
        d += __shfl_xor_sync(0xffffffffu, d, 16);
        d += __shfl_xor_sync(0xffffffffu, d, 8);
        d += __shfl_xor_sync(0xffffffffu, d, 4);
        d += __shfl_xor_sync(0xffffffffu, d, 2);
        d += __shfl_xor_sync(0xffffffffu, d, 1);
        d *= scale;
        if (lane == 0) sc[w][j] = d;
        mx = fmaxf(mx, d);
    }
    __syncwarp();

    float sum = 0.0f;
    for (int j = lane; j < cnt; j += 32) {
        float e = __expf(sc[w][j] - mx);
        sc[w][j] = e;
        sum += e;
    }
    sum += __shfl_xor_sync(0xffffffffu, sum, 16);
    sum += __shfl_xor_sync(0xffffffffu, sum, 8);
    sum += __shfl_xor_sync(0xffffffffu, sum, 4);
    sum += __shfl_xor_sync(0xffffffffu, sum, 2);
    sum += __shfl_xor_sync(0xffffffffu, sum, 1);
    float inv = 1.0f / sum;
    __syncwarp();

    float a0 = 0.f, a1 = 0.f, a2 = 0.f, a3 = 0.f;
    const float* vbase = g_v + (((size_t)(b * LL + s)) * NKV + kh) * HD;
    for (int j = 0; j < cnt; ++j) {
        float p = sc[w][j];
        const float* vp = vbase + (size_t)j * (NKV * HD);
        a0 += p * vp[lane];
        a1 += p * vp[lane + 32];
        a2 += p * vp[lane + 64];
        a3 += p * vp[lane + 96];
    }

    float* op = g_attn + (((size_t)(b * LL + i)) * NH + h) * HD;
    op[lane]      = a0 * inv;
    op[lane + 32] = a1 * inv;
    op[lane + 64] = a2 * inv;
    op[lane + 96] = a3 * inv;
}

// ---------------------------------------------------------------------------
// Launcher
// ---------------------------------------------------------------------------
extern "C" void kernel_launch(void* const* d_in, const int* in_sizes, int n_in,
                              void* d_out, int out_size)
{
    const float* x    = (const float*)d_in[0];
    const float* cosp = (const float*)d_in[1];
    const float* sinp = (const float*)d_in[2];
    const float* wq   = (const float*)d_in[3];
    const float* wk   = (const float*)d_in[4];
    const float* wv   = (const float*)d_in[5];
    const float* wo   = (const float*)d_in[6];
    float* out = (float*)d_out;

    float *pq, *pk, *pv, *pa;
    cudaGetSymbolAddress((void**)&pq, g_q);
    cudaGetSymbolAddress((void**)&pk, g_k);
    cudaGetSymbolAddress((void**)&pv, g_v);
    cudaGetSymbolAddress((void**)&pa, g_attn);

    // QKV projections: y = x @ W.T
    sgemm_abt<128, 128, 16, 8, 8><<<dim3(NH * HD / 128, MROWS / 128), 256>>>(x, wq, pq, DIM, NH * HD);
    sgemm_abt<128, 128, 16, 8, 8><<<dim3(NKV * HD / 128, MROWS / 128), 256>>>(x, wk, pk, DIM, NKV * HD);
    sgemm_abt<128, 128, 16, 8, 8><<<dim3(NKV * HD / 128, MROWS / 128), 256>>>(x, wv, pv, DIM, NKV * HD);

    // RoPE on q and k
    {
        int total = MROWS * (NH + NKV) * (HD / 2);
        rope_kernel<<<(total + 255) / 256, 256>>>(cosp, sinp);
    }

    // Sliding-window attention
    attn_kernel<<<BB * NH * (LL / 8), 256>>>();

    // Output projection: out = attn @ wo.T
    sgemm_abt<128, 128, 16, 8, 8><<<dim3(DIM / 128, MROWS / 128), 256>>>(pa, wo, out, NH * HD, DIM);
}

// round 3
// speedup vs baseline: 1.8629x; 1.8629x over previous
#include <cuda_runtime.h>
#include <cuda_bf16.h>
#include <cstdint>

// ---------------------------------------------------------------------------
// Problem constants
// ---------------------------------------------------------------------------
#define BB 2
#define LL 2048
#define DIM 2048
#define NH 16
#define NKV 8
#define HD 128
#define WIN 128
#define NREP (NH / NKV)
#define MROWS (BB * LL)        // 4096
#define KSPLIT (3 * DIM)       // 6144 bf16 (hi,hi,lo / hi,lo,hi concat)
#define BK 32
#define NT (KSPLIT / BK)       // 192 k-iterations

// ---------------------------------------------------------------------------
// Scratch (__device__ globals; no allocations allowed)
// ---------------------------------------------------------------------------
__device__ float g_q[(size_t)MROWS * NH * HD];
__device__ float g_k[(size_t)MROWS * NKV * HD];
__device__ float g_v[(size_t)MROWS * NKV * HD];
__device__ float g_attn[(size_t)MROWS * NH * HD];

__device__ __nv_bfloat16 g_xs [(size_t)MROWS * KSPLIT];
__device__ __nv_bfloat16 g_as [(size_t)MROWS * KSPLIT];
__device__ __nv_bfloat16 g_wqs[(size_t)(NH * HD) * KSPLIT];
__device__ __nv_bfloat16 g_wks[(size_t)(NKV * HD) * KSPLIT];
__device__ __nv_bfloat16 g_wvs[(size_t)(NKV * HD) * KSPLIT];
__device__ __nv_bfloat16 g_wos[(size_t)DIM * KSPLIT];

// ---------------------------------------------------------------------------
// PTX helpers (base sm_80+/sm_90 PTX only — NO "a"-suffix features)
// ---------------------------------------------------------------------------
__device__ __forceinline__ uint32_t smem_u32(const void* p) {
    uint32_t a;
    asm("{ .reg .u64 t; cvta.to.shared.u64 t, %1; cvt.u32.u64 %0, t; }" : "=r"(a) : "l"(p));
    return a;
}
__device__ __forceinline__ void cp_async16(uint32_t dst, const void* src) {
    asm volatile("cp.async.cg.shared.global [%0], [%1], 16;"
                 :: "r"(dst), "l"(__cvta_generic_to_global(src)) : "memory");
}
__device__ __forceinline__ void cp_commit() {
    asm volatile("cp.async.commit_group;" ::: "memory");
}
template <int N>
__device__ __forceinline__ void cp_wait() {
    asm volatile("cp.async.wait_group %0;" :: "n"(N) : "memory");
}
__device__ __forceinline__ void ldsm4(uint32_t* r, uint32_t addr) {
    asm volatile("ldmatrix.sync.aligned.m8n8.x4.shared.b16 {%0,%1,%2,%3}, [%4];"
                 : "=r"(r[0]), "=r"(r[1]), "=r"(r[2]), "=r"(r[3]) : "r"(addr));
}
__device__ __forceinline__ void mma16816(float* d, const uint32_t* a, const uint32_t* b) {
    asm volatile(
        "mma.sync.aligned.m16n8k16.row.col.f32.bf16.bf16.f32 "
        "{%0,%1,%2,%3}, {%4,%5,%6,%7}, {%8,%9}, {%0,%1,%2,%3};"
        : "+f"(d[0]), "+f"(d[1]), "+f"(d[2]), "+f"(d[3])
        : "r"(a[0]), "r"(a[1]), "r"(a[2]), "r"(a[3]), "r"(b[0]), "r"(b[1]));
}

// ---------------------------------------------------------------------------
// HMMA GEMM: C[m, n] = sum_k A'[m,k] * B'[n,k]
// CTA tile 128x128, BK=32, 3-stage cp.async pipeline, 8 warps (32x64 each).
// Smem rows padded to 40 bf16 (80 B) -> conflict-free ldmatrix.
// ---------------------------------------------------------------------------
#define SROW 40                          // elems per smem row (32 data + 8 pad)
#define TILE_BYTES (128 * SROW * 2)      // 10240
#define STAGE_BYTES (2 * TILE_BYTES)     // A + B = 20480
#define STAGES 3
#define GEMM_SMEM (STAGES * STAGE_BYTES) // 61440

__global__ __launch_bounds__(256, 2)
void gemm_bf16_mma(const __nv_bfloat16* __restrict__ Ag,
                   const __nv_bfloat16* __restrict__ Bg,
                   float* __restrict__ C, int ldc)
{
    extern __shared__ char smem_raw[];
    const uint32_t sb = smem_u32(smem_raw);
    const int t = threadIdx.x;
    const int lane = t & 31;
    const int wid = t >> 5;
    const int tile_m = blockIdx.y * 128;
    const int tile_n = blockIdx.x * 128;

    const int wm = (wid & 3) * 32;   // warp row offset within tile
    const int wn = (wid >> 2) * 64;  // warp col offset within tile

    // ldmatrix per-thread byte offsets (within a stage)
    const int tsel = lane >> 3, r = lane & 7;
    uint32_t aoff[2], boff[4];
#pragma unroll
    for (int i = 0; i < 2; ++i)
        aoff[i] = ((wm + 16 * i + (tsel & 1) * 8 + r) * SROW + ((tsel & 2) ? 8 : 0)) * 2;
#pragma unroll
    for (int j = 0; j < 4; ++j)
        boff[j] = TILE_BYTES +
                  ((wn + 16 * j + ((tsel & 2) ? 8 : 0) + r) * SROW + ((tsel & 1) ? 8 : 0)) * 2;

    // cp.async per-thread chunk coords (2 chunks of A + 2 of B per thread)
    // chunk idx -> row = idx>>2, c = idx&3 (16B chunks of a 64B row)
    float acc[2][8][4];
#pragma unroll
    for (int mi = 0; mi < 2; ++mi)
#pragma unroll
        for (int ni = 0; ni < 8; ++ni)
#pragma unroll
            for (int e = 0; e < 4; ++e) acc[mi][ni][e] = 0.0f;

    auto load_stage = [&](int st, int kt) {
        uint32_t base = sb + st * STAGE_BYTES;
#pragma unroll
        for (int i = 0; i < 2; ++i) {
            int idx = t + i * 256;
            int row = idx >> 2, c = idx & 3;
            cp_async16(base + row * (SROW * 2) + c * 16,
                       Ag + (size_t)(tile_m + row) * KSPLIT + kt * BK + c * 8);
            cp_async16(base + TILE_BYTES + row * (SROW * 2) + c * 16,
                       Bg + (size_t)(tile_n + row) * KSPLIT + kt * BK + c * 8);
        }
    };

    // Prologue: fill 2 stages
    load_stage(0, 0); cp_commit();
    load_stage(1, 1); cp_commit();

    for (int kt = 0; kt < NT; ++kt) {
        cp_wait<1>();
        __syncthreads();

        if (kt + 2 < NT) load_stage((kt + 2) % STAGES, kt + 2);
        cp_commit();

        uint32_t stb = sb + (kt % STAGES) * STAGE_BYTES;
#pragma unroll
        for (int ks = 0; ks < 2; ++ks) {
            uint32_t a[2][4], b[4][4];
            ldsm4(a[0], stb + aoff[0] + ks * 32);
            ldsm4(a[1], stb + aoff[1] + ks * 32);
#pragma unroll
            for (int j = 0; j < 4; ++j) ldsm4(b[j], stb + boff[j] + ks * 32);
#pragma unroll
            for (int mi = 0; mi < 2; ++mi)
#pragma unroll
                for (int j = 0; j < 4; ++j) {
                    mma16816(acc[mi][2 * j],     a[mi], &b[j][0]);
                    mma16816(acc[mi][2 * j + 1], a[mi], &b[j][2]);
                }
        }
    }

    // Epilogue: direct fp32 stores
    const int g = lane >> 2, c2 = (lane & 3) * 2;
#pragma unroll
    for (int mi = 0; mi < 2; ++mi) {
#pragma unroll
        for (int ni = 0; ni < 8; ++ni) {
            int row = tile_m + wm + 16 * mi + g;
            int col = tile_n + wn + 8 * ni + c2;
            *(float2*)(C + (size_t)row * ldc + col) =
                make_float2(acc[mi][ni][0], acc[mi][ni][1]);
            *(float2*)(C + (size_t)(row + 8) * ldc + col) =
                make_float2(acc[mi][ni][2], acc[mi][ni][3]);
        }
    }
}

// ---------------------------------------------------------------------------
// fp32 -> 3xBF16 split.  MODE 0 (A side): [hi | hi | lo].  MODE 1 (B side): [hi | lo | hi].
// ---------------------------------------------------------------------------
template <int MODE>
__global__ void split_bf16(const float* __restrict__ src, __nv_bfloat16* __restrict__ dst, int total)
{
    int i = blockIdx.x * blockDim.x + threadIdx.x;
    if (i >= total) return;
    int r = i >> 11;               // K = 2048
    int c = i & 2047;
    float v = src[i];
    __nv_bfloat16 h = __float2bfloat16(v);
    __nv_bfloat16 l = __float2bfloat16(v - __bfloat162float(h));
    size_t base = (size_t)r * KSPLIT + c;
    if (MODE == 0) { dst[base] = h; dst[base + 2048] = h; dst[base + 4096] = l; }
    else           { dst[base] = h; dst[base + 2048] = l; dst[base + 4096] = h; }
}

// ---------------------------------------------------------------------------
// RoPE (HF rotate_half) in-place on g_q / g_k.
// ---------------------------------------------------------------------------
__global__ void rope_kernel(const float* __restrict__ cosp, const float* __restrict__ sinp)
{
    int idx = blockIdx.x * blockDim.x + threadIdx.x;
    const int total = MROWS * (NH + NKV) * (HD / 2);
    if (idx >= total) return;

    int d = idx & 63;
    int rest = idx >> 6;
    int hh = rest % (NH + NKV);
    int row = rest / (NH + NKV);
    int l = row & (LL - 1);

    float c1 = cosp[l * HD + d];
    float s1 = sinp[l * HD + d];
    float c2 = cosp[l * HD + d + 64];
    float s2 = sinp[l * HD + d + 64];

    float* base;
    if (hh < NH) base = g_q + ((size_t)row * NH + hh) * HD;
    else         base = g_k + ((size_t)row * NKV + (hh - NH)) * HD;

    float t1 = base[d];
    float t2 = base[d + 64];
    base[d]      = t1 * c1 - t2 * s1;
    base[d + 64] = t2 * c2 + t1 * s2;
}

// ---------------------------------------------------------------------------
// Sliding-window causal attention (one warp per query, 8 queries/block).
// ---------------------------------------------------------------------------
__global__ __launch_bounds__(256)
void attn_kernel()
{
    const int lane = threadIdx.x & 31;
    const int w = threadIdx.x >> 5;
    const int bid = blockIdx.x;

    const int lt = bid % (LL / 8);
    const int bh = bid / (LL / 8);
    const int h = bh % NH;
    const int b = bh / NH;
    const int i = lt * 8 + w;
    const int kh = h / NREP;

    __shared__ float sc[8][136];

    const float* qp = g_q + (((size_t)(b * LL + i)) * NH + h) * HD;
    float q0 = qp[lane], q1 = qp[lane + 32], q2 = qp[lane + 64], q3 = qp[lane + 96];

    const int s = (i - WIN > 0) ? (i - WIN) : 0;
    const int cnt = i - s + 1;
    const float scale = 0.08838834764831845f;

    float mx = -1e30f;
    const float* kbase = g_k + (((size_t)(b * LL + s)) * NKV + kh) * HD;
    for (int j = 0; j < cnt; ++j) {
        const float* kp = kbase + (size_t)j * (NKV * HD);
        float d = q0 * kp[lane] + q1 * kp[lane + 32] + q2 * kp[lane + 64] + q3 * kp[lane + 96];
        d += __shfl_xor_sync(0xffffffffu, d, 16);
        d += __shfl_xor_sync(0xffffffffu, d, 8);
        d += __shfl_xor_sync(0xffffffffu, d, 4);
        d += __shfl_xor_sync(0xffffffffu, d, 2);
        d += __shfl_xor_sync(0xffffffffu, d, 1);
        d *= scale;
        if (lane == 0) sc[w][j] = d;
        mx = fmaxf(mx, d);
    }
    __syncwarp();

    float sum = 0.0f;
    for (int j = lane; j < cnt; j += 32) {
        float e = __expf(sc[w][j] - mx);
        sc[w][j] = e;
        sum += e;
    }
    sum += __shfl_xor_sync(0xffffffffu, sum, 16);
    sum += __shfl_xor_sync(0xffffffffu, sum, 8);
    sum += __shfl_xor_sync(0xffffffffu, sum, 4);
    sum += __shfl_xor_sync(0xffffffffu, sum, 2);
    sum += __shfl_xor_sync(0xffffffffu, sum, 1);
    float inv = 1.0f / sum;
    __syncwarp();

    float a0 = 0.f, a1 = 0.f, a2 = 0.f, a3 = 0.f;
    const float* vbase = g_v + (((size_t)(b * LL + s)) * NKV + kh) * HD;
    for (int j = 0; j < cnt; ++j) {
        float p = sc[w][j];
        const float* vp = vbase + (size_t)j * (NKV * HD);
        a0 += p * vp[lane];
        a1 += p * vp[lane + 32];
        a2 += p * vp[lane + 64];
        a3 += p * vp[lane + 96];
    }

    float* op = g_attn + (((size_t)(b * LL + i)) * NH + h) * HD;
    op[lane]      = a0 * inv;
    op[lane + 32] = a1 * inv;
    op[lane + 64] = a2 * inv;
    op[lane + 96] = a3 * inv;
}

// ---------------------------------------------------------------------------
// Launcher
// ---------------------------------------------------------------------------
extern "C" void kernel_launch(void* const* d_in, const int* in_sizes, int n_in,
                              void* d_out, int out_size)
{
    const float* x    = (const float*)d_in[0];
    const float* cosp = (const float*)d_in[1];
    const float* sinp = (const float*)d_in[2];
    const float* wq   = (const float*)d_in[3];
    const float* wk   = (const float*)d_in[4];
    const float* wv   = (const float*)d_in[5];
    const float* wo   = (const float*)d_in[6];
    float* out = (float*)d_out;

    float *pq, *pk, *pv, *pa;
    __nv_bfloat16 *pxs, *pas, *pwqs, *pwks, *pwvs, *pwos;
    cudaGetSymbolAddress((void**)&pq, g_q);
    cudaGetSymbolAddress((void**)&pk, g_k);
    cudaGetSymbolAddress((void**)&pv, g_v);
    cudaGetSymbolAddress((void**)&pa, g_attn);
    cudaGetSymbolAddress((void**)&pxs, g_xs);
    cudaGetSymbolAddress((void**)&pas, g_as);
    cudaGetSymbolAddress((void**)&pwqs, g_wqs);
    cudaGetSymbolAddress((void**)&pwks, g_wks);
    cudaGetSymbolAddress((void**)&pwvs, g_wvs);
    cudaGetSymbolAddress((void**)&pwos, g_wos);

    cudaFuncSetAttribute(gemm_bf16_mma, cudaFuncAttributeMaxDynamicSharedMemorySize, GEMM_SMEM);

    // 1) fp32 -> 3xBF16 splits
    {
        int tx = MROWS * DIM;
        split_bf16<0><<<(tx + 255) / 256, 256>>>(x, pxs, tx);
        int tq = NH * HD * DIM;
        split_bf16<1><<<(tq + 255) / 256, 256>>>(wq, pwqs, tq);
        int tk = NKV * HD * DIM;
        split_bf16<1><<<(tk + 255) / 256, 256>>>(wk, pwks, tk);
        split_bf16<1><<<(tk + 255) / 256, 256>>>(wv, pwvs, tk);
        int to = DIM * NH * HD;
        split_bf16<1><<<(to + 255) / 256, 256>>>(wo, pwos, to);
    }

    // 2) QKV projections on HMMA tensor cores
    gemm_bf16_mma<<<dim3((NH * HD) / 128, MROWS / 128), 256, GEMM_SMEM>>>(pxs, pwqs, pq, NH * HD);
    gemm_bf16_mma<<<dim3((NKV * HD) / 128, MROWS / 128), 256, GEMM_SMEM>>>(pxs, pwks, pk, NKV * HD);
    gemm_bf16_mma<<<dim3((NKV * HD) / 128, MROWS / 128), 256, GEMM_SMEM>>>(pxs, pwvs, pv, NKV * HD);

    // 3) RoPE
    {
        int total = MROWS * (NH + NKV) * (HD / 2);
        rope_kernel<<<(total + 255) / 256, 256>>>(cosp, sinp);
    }

    // 4) Sliding-window attention
    attn_kernel<<<BB * NH * (LL / 8), 256>>>();

    // 5) attn -> split -> output projection
    {
        int ta = MROWS * NH * HD;
        split_bf16<0><<<(ta + 255) / 256, 256>>>(pa, pas, ta);
    }
    gemm_bf16_mma<<<dim3(DIM / 128, MROWS / 128), 256, GEMM_SMEM>>>(pas, pwos, out, DIM);
}

// round 5
// speedup vs baseline: 2.2939x; 1.2314x over previous
#include <cuda_runtime.h>
#include <cuda_bf16.h>
#include <cstdint>

// ---------------------------------------------------------------------------
// Problem constants
// ---------------------------------------------------------------------------
#define BB 2
#define LL 2048
#define DIM 2048
#define NH 16
#define NKV 8
#define HD 128
#define WIN 128
#define NREP (NH / NKV)
#define MROWS (BB * LL)        // 4096
#define KSPLIT (3 * DIM)       // 6144 bf16 (hi,hi,lo / hi,lo,hi concat)
#define BK 32
#define NT (KSPLIT / BK)       // 192 k-iterations
#define NQKV (NH * HD + 2 * NKV * HD)   // 4096 fused QKV output cols

// ---------------------------------------------------------------------------
// Scratch (__device__ globals; no allocations allowed)
// ---------------------------------------------------------------------------
__device__ float g_q[(size_t)MROWS * NH * HD];
__device__ float g_k[(size_t)MROWS * NKV * HD];
__device__ float g_v[(size_t)MROWS * NKV * HD];
__device__ float g_attn[(size_t)MROWS * NH * HD];

__device__ __nv_bfloat16 g_xs   [(size_t)MROWS * KSPLIT];
__device__ __nv_bfloat16 g_as   [(size_t)MROWS * KSPLIT];
__device__ __nv_bfloat16 g_wqkvs[(size_t)NQKV * KSPLIT];     // [wq;wk;wv] split
__device__ __nv_bfloat16 g_wos  [(size_t)DIM * KSPLIT];

// ---------------------------------------------------------------------------
// PTX helpers (base sm_80+ PTX only — NO "a"-suffix features)
// ---------------------------------------------------------------------------
__device__ __forceinline__ uint32_t smem_u32(const void* p) {
    uint32_t a;
    asm("{ .reg .u64 t; cvta.to.shared.u64 t, %1; cvt.u32.u64 %0, t; }" : "=r"(a) : "l"(p));
    return a;
}
__device__ __forceinline__ void cp_async16(uint32_t dst, const void* src) {
    asm volatile("cp.async.cg.shared.global [%0], [%1], 16;"
                 :: "r"(dst), "l"(__cvta_generic_to_global(src)) : "memory");
}
__device__ __forceinline__ void cp_commit() {
    asm volatile("cp.async.commit_group;" ::: "memory");
}
template <int N>
__device__ __forceinline__ void cp_wait() {
    asm volatile("cp.async.wait_group %0;" :: "n"(N) : "memory");
}
__device__ __forceinline__ void ldsm4(uint32_t* r, uint32_t addr) {
    asm volatile("ldmatrix.sync.aligned.m8n8.x4.shared.b16 {%0,%1,%2,%3}, [%4];"
                 : "=r"(r[0]), "=r"(r[1]), "=r"(r[2]), "=r"(r[3]) : "r"(addr));
}
__device__ __forceinline__ void mma16816(float* d, const uint32_t* a, const uint32_t* b) {
    asm volatile(
        "mma.sync.aligned.m16n8k16.row.col.f32.bf16.bf16.f32 "
        "{%0,%1,%2,%3}, {%4,%5,%6,%7}, {%8,%9}, {%0,%1,%2,%3};"
        : "+f"(d[0]), "+f"(d[1]), "+f"(d[2]), "+f"(d[3])
        : "r"(a[0]), "r"(a[1]), "r"(a[2]), "r"(a[3]), "r"(b[0]), "r"(b[1]));
}

// ---------------------------------------------------------------------------
// HMMA GEMM: C[m, n] = sum_k A'[m,k] * B'[n,k]
// CTA tile 128x128, BK=32, 5-stage cp.async pipeline, 8 warps (32x64 each).
// QKV=1: fused epilogue writes q/k/v with RoPE applied (smem-staged).
// QKV=0: plain fp32 store to C.
// ---------------------------------------------------------------------------
#define SROW 40                          // elems per smem row (32 data + 8 pad)
#define TILE_BYTES (128 * SROW * 2)      // 10240
#define STAGE_BYTES (2 * TILE_BYTES)     // A + B = 20480
#define STAGES 5
#define GEMM_SMEM (STAGES * STAGE_BYTES) // 102400

template <int QKV>
__global__ __launch_bounds__(256, 2)
void gemm_bf16_mma(const __nv_bfloat16* __restrict__ Ag,
                   const __nv_bfloat16* __restrict__ Bg,
                   float* __restrict__ C, int ldc,
                   const float* __restrict__ cosp, const float* __restrict__ sinp)
{
    extern __shared__ char smem_raw[];
    const uint32_t sb = smem_u32(smem_raw);
    const int t = threadIdx.x;
    const int lane = t & 31;
    const int wid = t >> 5;
    const int tile_m = blockIdx.y * 128;
    const int tile_n = blockIdx.x * 128;

    const int wm = (wid & 3) * 32;   // warp row offset within tile
    const int wn = (wid >> 2) * 64;  // warp col offset within tile

    // ldmatrix per-thread byte offsets (within a stage)
    const int tsel = lane >> 3, r = lane & 7;
    uint32_t aoff[2], boff[4];
#pragma unroll
    for (int i = 0; i < 2; ++i)
        aoff[i] = ((wm + 16 * i + (tsel & 1) * 8 + r) * SROW + ((tsel & 2) ? 8 : 0)) * 2;
#pragma unroll
    for (int j = 0; j < 4; ++j)
        boff[j] = TILE_BYTES +
                  ((wn + 16 * j + ((tsel & 2) ? 8 : 0) + r) * SROW + ((tsel & 1) ? 8 : 0)) * 2;

    float acc[2][8][4];
#pragma unroll
    for (int mi = 0; mi < 2; ++mi)
#pragma unroll
        for (int ni = 0; ni < 8; ++ni)
#pragma unroll
            for (int e = 0; e < 4; ++e) acc[mi][ni][e] = 0.0f;

    auto load_stage = [&](int st, int kt) {
        uint32_t base = sb + st * STAGE_BYTES;
#pragma unroll
        for (int i = 0; i < 2; ++i) {
            int idx = t + i * 256;
            int row = idx >> 2, c = idx & 3;
            cp_async16(base + row * (SROW * 2) + c * 16,
                       Ag + (size_t)(tile_m + row) * KSPLIT + kt * BK + c * 8);
            cp_async16(base + TILE_BYTES + row * (SROW * 2) + c * 16,
                       Bg + (size_t)(tile_n + row) * KSPLIT + kt * BK + c * 8);
        }
    };

    // Prologue: fill 4 of 5 stages
#pragma unroll
    for (int s = 0; s < STAGES - 1; ++s) { load_stage(s, s); cp_commit(); }

    int cs_idx = 0, ld_idx = STAGES - 1;
    for (int kt = 0; kt < NT; ++kt) {
        cp_wait<STAGES - 2>();      // oldest pending group (stage kt) complete
        __syncthreads();

        if (kt + STAGES - 1 < NT) load_stage(ld_idx, kt + STAGES - 1);
        cp_commit();
        if (++ld_idx == STAGES) ld_idx = 0;

        uint32_t stb = sb + cs_idx * STAGE_BYTES;
        if (++cs_idx == STAGES) cs_idx = 0;
#pragma unroll
        for (int ks = 0; ks < 2; ++ks) {
            uint32_t a[2][4], b[4][4];
            ldsm4(a[0], stb + aoff[0] + ks * 32);
            ldsm4(a[1], stb + aoff[1] + ks * 32);
#pragma unroll
            for (int j = 0; j < 4; ++j) ldsm4(b[j], stb + boff[j] + ks * 32);
#pragma unroll
            for (int mi = 0; mi < 2; ++mi)
#pragma unroll
                for (int j = 0; j < 4; ++j) {
                    mma16816(acc[mi][2 * j],     a[mi], &b[j][0]);
                    mma16816(acc[mi][2 * j + 1], a[mi], &b[j][2]);
                }
        }
    }

    const int g = lane >> 2, c2 = (lane & 3) * 2;

    if (QKV) {
        // Stage C tile in smem, then apply RoPE (q,k) or copy (v)
        __syncthreads();
        float* cs = (float*)smem_raw;   // 128 x 132
#pragma unroll
        for (int mi = 0; mi < 2; ++mi)
#pragma unroll
            for (int ni = 0; ni < 8; ++ni) {
                int rr = wm + 16 * mi + g;
                int cc = wn + 8 * ni + c2;
                *(float2*)&cs[rr * 132 + cc]       = make_float2(acc[mi][ni][0], acc[mi][ni][1]);
                *(float2*)&cs[(rr + 8) * 132 + cc] = make_float2(acc[mi][ni][2], acc[mi][ni][3]);
            }
        __syncthreads();

        float* dst;
        int ldd, col0;
        bool rope;
        if (tile_n < NH * HD)                 { dst = g_q; ldd = NH * HD;  col0 = tile_n;                  rope = true;  }
        else if (tile_n < NH * HD + NKV * HD) { dst = g_k; ldd = NKV * HD; col0 = tile_n - NH * HD;        rope = true;  }
        else                                  { dst = g_v; ldd = NKV * HD; col0 = tile_n - NH*HD - NKV*HD; rope = false; }

        if (rope) {
            for (int it = t; it < 128 * 64; it += 256) {
                int rr = it >> 6, d = it & 63;
                int grow = tile_m + rr;
                int l = grow & (LL - 1);
                float t1 = cs[rr * 132 + d];
                float t2 = cs[rr * 132 + d + 64];
                float c1 = cosp[l * HD + d],       s1 = sinp[l * HD + d];
                float c2f = cosp[l * HD + d + 64], s2 = sinp[l * HD + d + 64];
                dst[(size_t)grow * ldd + col0 + d]      = t1 * c1 - t2 * s1;
                dst[(size_t)grow * ldd + col0 + d + 64] = t2 * c2f + t1 * s2;
            }
        } else {
            for (int it = t; it < 128 * 32; it += 256) {
                int rr = it >> 5, d = (it & 31) * 4;
                float4 v = *(float4*)&cs[rr * 132 + d];
                *(float4*)&dst[(size_t)(tile_m + rr) * ldd + col0 + d] = v;
            }
        }
    } else {
        // Plain fp32 store
#pragma unroll
        for (int mi = 0; mi < 2; ++mi) {
#pragma unroll
            for (int ni = 0; ni < 8; ++ni) {
                int row = tile_m + wm + 16 * mi + g;
                int col = tile_n + wn + 8 * ni + c2;
                *(float2*)(C + (size_t)row * ldc + col) =
                    make_float2(acc[mi][ni][0], acc[mi][ni][1]);
                *(float2*)(C + (size_t)(row + 8) * ldc + col) =
                    make_float2(acc[mi][ni][2], acc[mi][ni][3]);
            }
        }
    }
}

// ---------------------------------------------------------------------------
// fp32 -> 3xBF16 split, vectorized x4.
// MODE 0 (A side): [hi | hi | lo].  MODE 1 (B side): [hi | lo | hi].
// total4 = element_count / 4 ; source K = 2048 per row.
// ---------------------------------------------------------------------------
template <int MODE>
__global__ void split_bf16(const float* __restrict__ src, __nv_bfloat16* __restrict__ dst, int total4)
{
    int i = blockIdx.x * blockDim.x + threadIdx.x;
    if (i >= total4) return;
    int e = i * 4;
    int r = e >> 11;
    int c = e & 2047;
    float4 v = *(const float4*)(src + e);

    __nv_bfloat16 h[4], l[4];
    float vv[4] = {v.x, v.y, v.z, v.w};
#pragma unroll
    for (int j = 0; j < 4; ++j) {
        h[j] = __float2bfloat16(vv[j]);
        l[j] = __float2bfloat16(vv[j] - __bfloat162float(h[j]));
    }
    uint2 hp = *(uint2*)h;
    uint2 lp = *(uint2*)l;

    size_t base = (size_t)r * KSPLIT + c;
    *(uint2*)&dst[base] = hp;
    if (MODE == 0) { *(uint2*)&dst[base + 2048] = hp; *(uint2*)&dst[base + 4096] = lp; }
    else           { *(uint2*)&dst[base + 2048] = lp; *(uint2*)&dst[base + 4096] = hp; }
}

// ---------------------------------------------------------------------------
// Sliding-window causal attention (one warp per query, 8 queries/block).
// float4 K/V loads, 2-key unrolled shfl reductions.
// ---------------------------------------------------------------------------
__global__ __launch_bounds__(256)
void attn_kernel()
{
    const int lane = threadIdx.x & 31;
    const int w = threadIdx.x >> 5;
    const int bid = blockIdx.x;

    const int lt = bid % (LL / 8);
    const int bh = bid / (LL / 8);
    const int h = bh % NH;
    const int b = bh / NH;
    const int i = lt * 8 + w;
    const int kh = h / NREP;
    const int KVD = NKV * HD;   // 1024

    __shared__ float sc[8][136];

    const float* qp = g_q + (((size_t)(b * LL + i)) * NH + h) * HD;
    float4 q = *(const float4*)(qp + 4 * lane);

    const int s = (i - WIN > 0) ? (i - WIN) : 0;
    const int cnt = i - s + 1;
    const float scale = 0.08838834764831845f;

    float mx = -1e30f;
    const float* kbase = g_k + ((size_t)(b * LL + s)) * KVD + kh * HD + 4 * lane;
    int j = 0;
    for (; j + 2 <= cnt; j += 2) {
        float4 k0 = *(const float4*)(kbase + (size_t)j * KVD);
        float4 k1 = *(const float4*)(kbase + (size_t)(j + 1) * KVD);
        float d0 = q.x * k0.x + q.y * k0.y + q.z * k0.z + q.w * k0.w;
        float d1 = q.x * k1.x + q.y * k1.y + q.z * k1.z + q.w * k1.w;
#pragma unroll
        for (int off = 16; off; off >>= 1) {
            d0 += __shfl_xor_sync(0xffffffffu, d0, off);
            d1 += __shfl_xor_sync(0xffffffffu, d1, off);
        }
        d0 *= scale; d1 *= scale;
        if (lane == 0) { sc[w][j] = d0; sc[w][j + 1] = d1; }
        mx = fmaxf(mx, fmaxf(d0, d1));
    }
    if (j < cnt) {
        float4 k0 = *(const float4*)(kbase + (size_t)j * KVD);
        float d0 = q.x * k0.x + q.y * k0.y + q.z * k0.z + q.w * k0.w;
#pragma unroll
        for (int off = 16; off; off >>= 1) d0 += __shfl_xor_sync(0xffffffffu, d0, off);
        d0 *= scale;
        if (lane == 0) sc[w][j] = d0;
        mx = fmaxf(mx, d0);
    }
    __syncwarp();

    float sum = 0.0f;
    for (int jj = lane; jj < cnt; jj += 32) {
        float e = __expf(sc[w][jj] - mx);
        sc[w][jj] = e;
        sum += e;
    }
#pragma unroll
    for (int off = 16; off; off >>= 1) sum += __shfl_xor_sync(0xffffffffu, sum, off);
    float inv = 1.0f / sum;
    __syncwarp();

    float ax = 0.f, ay = 0.f, az = 0.f, aw = 0.f;
    const float* vbase = g_v + ((size_t)(b * LL + s)) * KVD + kh * HD + 4 * lane;
    j = 0;
    for (; j + 2 <= cnt; j += 2) {
        float p0 = sc[w][j], p1 = sc[w][j + 1];
        float4 v0 = *(const float4*)(vbase + (size_t)j * KVD);
        float4 v1 = *(const float4*)(vbase + (size_t)(j + 1) * KVD);
        ax += p0 * v0.x + p1 * v1.x;
        ay += p0 * v0.y + p1 * v1.y;
        az += p0 * v0.z + p1 * v1.z;
        aw += p0 * v0.w + p1 * v1.w;
    }
    if (j < cnt) {
        float p0 = sc[w][j];
        float4 v0 = *(const float4*)(vbase + (size_t)j * KVD);
        ax += p0 * v0.x; ay += p0 * v0.y; az += p0 * v0.z; aw += p0 * v0.w;
    }

    float* op = g_attn + (((size_t)(b * LL + i)) * NH + h) * HD + 4 * lane;
    *(float4*)op = make_float4(ax * inv, ay * inv, az * inv, aw * inv);
}

// ---------------------------------------------------------------------------
// Launcher
// ---------------------------------------------------------------------------
extern "C" void kernel_launch(void* const* d_in, const int* in_sizes, int n_in,
                              void* d_out, int out_size)
{
    const float* x    = (const float*)d_in[0];
    const float* cosp = (const float*)d_in[1];
    const float* sinp = (const float*)d_in[2];
    const float* wq   = (const float*)d_in[3];
    const float* wk   = (const float*)d_in[4];
    const float* wv   = (const float*)d_in[5];
    const float* wo   = (const float*)d_in[6];
    float* out = (float*)d_out;

    float* pa;
    __nv_bfloat16 *pxs, *pas, *pwqkvs, *pwos;
    cudaGetSymbolAddress((void**)&pa, g_attn);
    cudaGetSymbolAddress((void**)&pxs, g_xs);
    cudaGetSymbolAddress((void**)&pas, g_as);
    cudaGetSymbolAddress((void**)&pwqkvs, g_wqkvs);
    cudaGetSymbolAddress((void**)&pwos, g_wos);

    cudaFuncSetAttribute(gemm_bf16_mma<1>, cudaFuncAttributeMaxDynamicSharedMemorySize, GEMM_SMEM);
    cudaFuncSetAttribute(gemm_bf16_mma<0>, cudaFuncAttributeMaxDynamicSharedMemorySize, GEMM_SMEM);

    // 1) fp32 -> 3xBF16 splits (vectorized)
    {
        int tx = (MROWS * DIM) / 4;
        split_bf16<0><<<(tx + 255) / 256, 256>>>(x, pxs, tx);
        int tq = (NH * HD * DIM) / 4;
        split_bf16<1><<<(tq + 255) / 256, 256>>>(wq, pwqkvs, tq);
        int tk = (NKV * HD * DIM) / 4;
        split_bf16<1><<<(tk + 255) / 256, 256>>>(wk, pwqkvs + (size_t)(NH * HD) * KSPLIT, tk);
        split_bf16<1><<<(tk + 255) / 256, 256>>>(wv, pwqkvs + (size_t)(NH * HD + NKV * HD) * KSPLIT, tk);
        int to = (DIM * NH * HD) / 4;
        split_bf16<1><<<(to + 255) / 256, 256>>>(wo, pwos, to);
    }

    // 2) Fused QKV projection + RoPE epilogue
    gemm_bf16_mma<1><<<dim3(NQKV / 128, MROWS / 128), 256, GEMM_SMEM>>>(
        pxs, pwqkvs, nullptr, 0, cosp, sinp);

    // 3) Sliding-window attention
    attn_kernel<<<BB * NH * (LL / 8), 256>>>();

    // 4) attn -> split -> output projection
    {
        int ta = (MROWS * NH * HD) / 4;
        split_bf16<0><<<(ta + 255) / 256, 256>>>(pa, pas, ta);
    }
    gemm_bf16_mma<0><<<dim3(DIM / 128, MROWS / 128), 256, GEMM_SMEM>>>(
        pas, pwos, out, DIM, nullptr, nullptr);
}

// round 6
// speedup vs baseline: 2.6965x; 1.1755x over previous
#include <cuda_runtime.h>
#include <cuda_bf16.h>
#include <cuda_fp16.h>
#include <cstdint>

// ---------------------------------------------------------------------------
// Problem constants
// ---------------------------------------------------------------------------
#define BB 2
#define LL 2048
#define DIM 2048
#define NH 16
#define NKV 8
#define HD 128
#define WIN 128
#define NREP (NH / NKV)
#define MROWS (BB * LL)        // 4096
#define KSPLIT (3 * DIM)       // 6144 bf16 (hi,hi,lo / hi,lo,hi concat)
#define BK 32
#define NQKV (NH * HD + 2 * NKV * HD)   // 4096 fused QKV output cols

// ---------------------------------------------------------------------------
// Scratch (__device__ globals; no allocations allowed)
// ---------------------------------------------------------------------------
__device__ float g_q[(size_t)MROWS * NH * HD];
__device__ float g_k[(size_t)MROWS * NKV * HD];
__device__ float g_v[(size_t)MROWS * NKV * HD];

__device__ __half g_ao16[(size_t)MROWS * (NH * HD)];          // attn out, fp16
__device__ __half g_wo16[(size_t)DIM * (NH * HD)];            // wo, fp16

__device__ __nv_bfloat16 g_xs   [(size_t)MROWS * KSPLIT];
__device__ __nv_bfloat16 g_wqkvs[(size_t)NQKV * KSPLIT];      // [wq;wk;wv] split

// ---------------------------------------------------------------------------
// PTX helpers (base sm_80+ PTX only — NO "a"-suffix features)
// ---------------------------------------------------------------------------
__device__ __forceinline__ uint32_t smem_u32(const void* p) {
    uint32_t a;
    asm("{ .reg .u64 t; cvta.to.shared.u64 t, %1; cvt.u32.u64 %0, t; }" : "=r"(a) : "l"(p));
    return a;
}
__device__ __forceinline__ void cp_async16(uint32_t dst, const void* src) {
    asm volatile("cp.async.cg.shared.global [%0], [%1], 16;"
                 :: "r"(dst), "l"(__cvta_generic_to_global(src)) : "memory");
}
__device__ __forceinline__ void cp_commit() {
    asm volatile("cp.async.commit_group;" ::: "memory");
}
template <int N>
__device__ __forceinline__ void cp_wait() {
    asm volatile("cp.async.wait_group %0;" :: "n"(N) : "memory");
}
__device__ __forceinline__ void ldsm4(uint32_t* r, uint32_t addr) {
    asm volatile("ldmatrix.sync.aligned.m8n8.x4.shared.b16 {%0,%1,%2,%3}, [%4];"
                 : "=r"(r[0]), "=r"(r[1]), "=r"(r[2]), "=r"(r[3]) : "r"(addr));
}
template <int FP16>
__device__ __forceinline__ void mma16816(float* d, const uint32_t* a, const uint32_t* b) {
    if (FP16)
        asm volatile(
            "mma.sync.aligned.m16n8k16.row.col.f32.f16.f16.f32 "
            "{%0,%1,%2,%3}, {%4,%5,%6,%7}, {%8,%9}, {%0,%1,%2,%3};"
            : "+f"(d[0]), "+f"(d[1]), "+f"(d[2]), "+f"(d[3])
            : "r"(a[0]), "r"(a[1]), "r"(a[2]), "r"(a[3]), "r"(b[0]), "r"(b[1]));
    else
        asm volatile(
            "mma.sync.aligned.m16n8k16.row.col.f32.bf16.bf16.f32 "
            "{%0,%1,%2,%3}, {%4,%5,%6,%7}, {%8,%9}, {%0,%1,%2,%3};"
            : "+f"(d[0]), "+f"(d[1]), "+f"(d[2]), "+f"(d[3])
            : "r"(a[0]), "r"(a[1]), "r"(a[2]), "r"(a[3]), "r"(b[0]), "r"(b[1]));
}

// ---------------------------------------------------------------------------
// HMMA GEMM: C[m, n] = sum_k A[m,k] * B[n,k]   (operands 2-byte: bf16 or fp16)
// CTA tile 128x128, BK=32, 5-stage cp.async pipeline, 8 warps (32x64 each).
// QKV=1: fused epilogue writes q/k/v with RoPE applied (smem-staged).
// QKV=0: plain fp32 store to C.
// ---------------------------------------------------------------------------
#define SROW 40                          // elems per smem row (32 data + 8 pad)
#define TILE_BYTES (128 * SROW * 2)      // 10240
#define STAGE_BYTES (2 * TILE_BYTES)     // A + B = 20480
#define STAGES 5
#define GEMM_SMEM (STAGES * STAGE_BYTES) // 102400

template <int QKV, int FP16>
__global__ __launch_bounds__(256, 2)
void gemm_mma(const uint16_t* __restrict__ Ag,
              const uint16_t* __restrict__ Bg,
              float* __restrict__ C, int ldc, int kdim,
              const float* __restrict__ cosp, const float* __restrict__ sinp)
{
    extern __shared__ char smem_raw[];
    const uint32_t sb = smem_u32(smem_raw);
    const int t = threadIdx.x;
    const int lane = t & 31;
    const int wid = t >> 5;
    const int tile_m = blockIdx.y * 128;
    const int tile_n = blockIdx.x * 128;
    const int NTt = kdim / BK;

    const int wm = (wid & 3) * 32;   // warp row offset within tile
    const int wn = (wid >> 2) * 64;  // warp col offset within tile

    // ldmatrix per-thread byte offsets (within a stage)
    const int tsel = lane >> 3, r = lane & 7;
    uint32_t aoff[2], boff[4];
#pragma unroll
    for (int i = 0; i < 2; ++i)
        aoff[i] = ((wm + 16 * i + (tsel & 1) * 8 + r) * SROW + ((tsel & 2) ? 8 : 0)) * 2;
#pragma unroll
    for (int j = 0; j < 4; ++j)
        boff[j] = TILE_BYTES +
                  ((wn + 16 * j + ((tsel & 2) ? 8 : 0) + r) * SROW + ((tsel & 1) ? 8 : 0)) * 2;

    float acc[2][8][4];
#pragma unroll
    for (int mi = 0; mi < 2; ++mi)
#pragma unroll
        for (int ni = 0; ni < 8; ++ni)
#pragma unroll
            for (int e = 0; e < 4; ++e) acc[mi][ni][e] = 0.0f;

    auto load_stage = [&](int st, int kt) {
        uint32_t base = sb + st * STAGE_BYTES;
#pragma unroll
        for (int i = 0; i < 2; ++i) {
            int idx = t + i * 256;
            int row = idx >> 2, c = idx & 3;
            cp_async16(base + row * (SROW * 2) + c * 16,
                       Ag + (size_t)(tile_m + row) * kdim + kt * BK + c * 8);
            cp_async16(base + TILE_BYTES + row * (SROW * 2) + c * 16,
                       Bg + (size_t)(tile_n + row) * kdim + kt * BK + c * 8);
        }
    };

    // Prologue: fill 4 of 5 stages
#pragma unroll
    for (int s = 0; s < STAGES - 1; ++s) { load_stage(s, s); cp_commit(); }

    int cs_idx = 0, ld_idx = STAGES - 1;
    for (int kt = 0; kt < NTt; ++kt) {
        cp_wait<STAGES - 2>();
        __syncthreads();

        if (kt + STAGES - 1 < NTt) load_stage(ld_idx, kt + STAGES - 1);
        cp_commit();
        if (++ld_idx == STAGES) ld_idx = 0;

        uint32_t stb = sb + cs_idx * STAGE_BYTES;
        if (++cs_idx == STAGES) cs_idx = 0;
#pragma unroll
        for (int ks = 0; ks < 2; ++ks) {
            uint32_t a[2][4], b[4][4];
            ldsm4(a[0], stb + aoff[0] + ks * 32);
            ldsm4(a[1], stb + aoff[1] + ks * 32);
#pragma unroll
            for (int j = 0; j < 4; ++j) ldsm4(b[j], stb + boff[j] + ks * 32);
#pragma unroll
            for (int mi = 0; mi < 2; ++mi)
#pragma unroll
                for (int j = 0; j < 4; ++j) {
                    mma16816<FP16>(acc[mi][2 * j],     a[mi], &b[j][0]);
                    mma16816<FP16>(acc[mi][2 * j + 1], a[mi], &b[j][2]);
                }
        }
    }

    const int g = lane >> 2, c2 = (lane & 3) * 2;

    if (QKV) {
        // Stage C tile in smem, then apply RoPE (q,k) or copy (v)
        __syncthreads();
        float* cs = (float*)smem_raw;   // 128 x 132
#pragma unroll
        for (int mi = 0; mi < 2; ++mi)
#pragma unroll
            for (int ni = 0; ni < 8; ++ni) {
                int rr = wm + 16 * mi + g;
                int cc = wn + 8 * ni + c2;
                *(float2*)&cs[rr * 132 + cc]       = make_float2(acc[mi][ni][0], acc[mi][ni][1]);
                *(float2*)&cs[(rr + 8) * 132 + cc] = make_float2(acc[mi][ni][2], acc[mi][ni][3]);
            }
        __syncthreads();

        float* dst;
        int ldd, col0;
        bool rope;
        if (tile_n < NH * HD)                 { dst = g_q; ldd = NH * HD;  col0 = tile_n;                  rope = true;  }
        else if (tile_n < NH * HD + NKV * HD) { dst = g_k; ldd = NKV * HD; col0 = tile_n - NH * HD;        rope = true;  }
        else                                  { dst = g_v; ldd = NKV * HD; col0 = tile_n - NH*HD - NKV*HD; rope = false; }

        if (rope) {
            for (int it = t; it < 128 * 64; it += 256) {
                int rr = it >> 6, d = it & 63;
                int grow = tile_m + rr;
                int l = grow & (LL - 1);
                float t1 = cs[rr * 132 + d];
                float t2 = cs[rr * 132 + d + 64];
                float c1 = cosp[l * HD + d],       s1 = sinp[l * HD + d];
                float c2f = cosp[l * HD + d + 64], s2 = sinp[l * HD + d + 64];
                dst[(size_t)grow * ldd + col0 + d]      = t1 * c1 - t2 * s1;
                dst[(size_t)grow * ldd + col0 + d + 64] = t2 * c2f + t1 * s2;
            }
        } else {
            for (int it = t; it < 128 * 32; it += 256) {
                int rr = it >> 5, d = (it & 31) * 4;
                float4 v = *(float4*)&cs[rr * 132 + d];
                *(float4*)&dst[(size_t)(tile_m + rr) * ldd + col0 + d] = v;
            }
        }
    } else {
        // Plain fp32 store
#pragma unroll
        for (int mi = 0; mi < 2; ++mi) {
#pragma unroll
            for (int ni = 0; ni < 8; ++ni) {
                int row = tile_m + wm + 16 * mi + g;
                int col = tile_n + wn + 8 * ni + c2;
                *(float2*)(C + (size_t)row * ldc + col) =
                    make_float2(acc[mi][ni][0], acc[mi][ni][1]);
                *(float2*)(C + (size_t)(row + 8) * ldc + col) =
                    make_float2(acc[mi][ni][2], acc[mi][ni][3]);
            }
        }
    }
}

// ---------------------------------------------------------------------------
// fp32 -> 3xBF16 split, vectorized x4.
// MODE 0 (A side): [hi | hi | lo].  MODE 1 (B side): [hi | lo | hi].
// ---------------------------------------------------------------------------
template <int MODE>
__global__ void split_bf16(const float* __restrict__ src, __nv_bfloat16* __restrict__ dst, int total4)
{
    int i = blockIdx.x * blockDim.x + threadIdx.x;
    if (i >= total4) return;
    int e = i * 4;
    int r = e >> 11;
    int c = e & 2047;
    float4 v = *(const float4*)(src + e);

    __nv_bfloat16 h[4], l[4];
    float vv[4] = {v.x, v.y, v.z, v.w};
#pragma unroll
    for (int j = 0; j < 4; ++j) {
        h[j] = __float2bfloat16(vv[j]);
        l[j] = __float2bfloat16(vv[j] - __bfloat162float(h[j]));
    }
    uint2 hp = *(uint2*)h;
    uint2 lp = *(uint2*)l;

    size_t base = (size_t)r * KSPLIT + c;
    *(uint2*)&dst[base] = hp;
    if (MODE == 0) { *(uint2*)&dst[base + 2048] = hp; *(uint2*)&dst[base + 4096] = lp; }
    else           { *(uint2*)&dst[base + 2048] = lp; *(uint2*)&dst[base + 4096] = hp; }
}

// ---------------------------------------------------------------------------
// fp32 -> fp16 convert (for wo), vectorized x4.
// ---------------------------------------------------------------------------
__global__ void conv_fp16(const float* __restrict__ src, __half* __restrict__ dst, int total4)
{
    int i = blockIdx.x * blockDim.x + threadIdx.x;
    if (i >= total4) return;
    float4 v = *(const float4*)(src + i * 4);
    __half2 h0 = __floats2half2_rn(v.x, v.y);
    __half2 h1 = __floats2half2_rn(v.z, v.w);
    *(uint2*)(dst + (size_t)i * 4) = make_uint2(*(uint32_t*)&h0, *(uint32_t*)&h1);
}

// ---------------------------------------------------------------------------
// Sliding-window causal attention.
// 512 threads: 16 warps = 8 positions x 2 GQA heads sharing one KV head.
// Writes fp16 directly (feeds the fp16 O-projection).
// ---------------------------------------------------------------------------
__global__ __launch_bounds__(512)
void attn_kernel()
{
    const int lane = threadIdx.x & 31;
    const int w = threadIdx.x >> 5;       // 0..15
    const int bid = blockIdx.x;

    const int lt = bid % (LL / 8);
    const int bkh = bid / (LL / 8);
    const int kh = bkh % NKV;
    const int b = bkh / NKV;
    const int i = lt * 8 + (w >> 1);       // query position
    const int h = kh * NREP + (w & 1);     // query head
    const int KVD = NKV * HD;              // 1024

    __shared__ float sc[16][136];

    const float* qp = g_q + (((size_t)(b * LL + i)) * NH + h) * HD;
    float4 q = *(const float4*)(qp + 4 * lane);

    const int s = (i - WIN > 0) ? (i - WIN) : 0;
    const int cnt = i - s + 1;
    const float scale = 0.08838834764831845f;

    float mx = -1e30f;
    const float* kbase = g_k + ((size_t)(b * LL + s)) * KVD + kh * HD + 4 * lane;
    int j = 0;
    for (; j + 2 <= cnt; j += 2) {
        float4 k0 = *(const float4*)(kbase + (size_t)j * KVD);
        float4 k1 = *(const float4*)(kbase + (size_t)(j + 1) * KVD);
        float d0 = q.x * k0.x + q.y * k0.y + q.z * k0.z + q.w * k0.w;
        float d1 = q.x * k1.x + q.y * k1.y + q.z * k1.z + q.w * k1.w;
#pragma unroll
        for (int off = 16; off; off >>= 1) {
            d0 += __shfl_xor_sync(0xffffffffu, d0, off);
            d1 += __shfl_xor_sync(0xffffffffu, d1, off);
        }
        d0 *= scale; d1 *= scale;
        if (lane == 0) { sc[w][j] = d0; sc[w][j + 1] = d1; }
        mx = fmaxf(mx, fmaxf(d0, d1));
    }
    if (j < cnt) {
        float4 k0 = *(const float4*)(kbase + (size_t)j * KVD);
        float d0 = q.x * k0.x + q.y * k0.y + q.z * k0.z + q.w * k0.w;
#pragma unroll
        for (int off = 16; off; off >>= 1) d0 += __shfl_xor_sync(0xffffffffu, d0, off);
        d0 *= scale;
        if (lane == 0) sc[w][j] = d0;
        mx = fmaxf(mx, d0);
    }
    __syncwarp();

    float sum = 0.0f;
    for (int jj = lane; jj < cnt; jj += 32) {
        float e = __expf(sc[w][jj] - mx);
        sc[w][jj] = e;
        sum += e;
    }
#pragma unroll
    for (int off = 16; off; off >>= 1) sum += __shfl_xor_sync(0xffffffffu, sum, off);
    float inv = 1.0f / sum;
    __syncwarp();

    float ax = 0.f, ay = 0.f, az = 0.f, aw = 0.f;
    const float* vbase = g_v + ((size_t)(b * LL + s)) * KVD + kh * HD + 4 * lane;
    j = 0;
    for (; j + 2 <= cnt; j += 2) {
        float p0 = sc[w][j], p1 = sc[w][j + 1];
        float4 v0 = *(const float4*)(vbase + (size_t)j * KVD);
        float4 v1 = *(const float4*)(vbase + (size_t)(j + 1) * KVD);
        ax += p0 * v0.x + p1 * v1.x;
        ay += p0 * v0.y + p1 * v1.y;
        az += p0 * v0.z + p1 * v1.z;
        aw += p0 * v0.w + p1 * v1.w;
    }
    if (j < cnt) {
        float p0 = sc[w][j];
        float4 v0 = *(const float4*)(vbase + (size_t)j * KVD);
        ax += p0 * v0.x; ay += p0 * v0.y; az += p0 * v0.z; aw += p0 * v0.w;
    }

    // fp16 output (row = token, col = h*HD + 4*lane)
    __half* op = g_ao16 + ((size_t)(b * LL + i)) * (NH * HD) + h * HD + 4 * lane;
    __half2 o0 = __floats2half2_rn(ax * inv, ay * inv);
    __half2 o1 = __floats2half2_rn(az * inv, aw * inv);
    *(uint2*)op = make_uint2(*(uint32_t*)&o0, *(uint32_t*)&o1);
}

// ---------------------------------------------------------------------------
// Launcher
// ---------------------------------------------------------------------------
extern "C" void kernel_launch(void* const* d_in, const int* in_sizes, int n_in,
                              void* d_out, int out_size)
{
    const float* x    = (const float*)d_in[0];
    const float* cosp = (const float*)d_in[1];
    const float* sinp = (const float*)d_in[2];
    const float* wq   = (const float*)d_in[3];
    const float* wk   = (const float*)d_in[4];
    const float* wv   = (const float*)d_in[5];
    const float* wo   = (const float*)d_in[6];
    float* out = (float*)d_out;

    __nv_bfloat16 *pxs, *pwqkvs;
    __half *pao16, *pwo16;
    cudaGetSymbolAddress((void**)&pxs, g_xs);
    cudaGetSymbolAddress((void**)&pwqkvs, g_wqkvs);
    cudaGetSymbolAddress((void**)&pao16, g_ao16);
    cudaGetSymbolAddress((void**)&pwo16, g_wo16);

    cudaFuncSetAttribute((const void*)gemm_mma<1, 0>, cudaFuncAttributeMaxDynamicSharedMemorySize, GEMM_SMEM);
    cudaFuncSetAttribute((const void*)gemm_mma<0, 1>, cudaFuncAttributeMaxDynamicSharedMemorySize, GEMM_SMEM);

    // 1) fp32 -> 3xBF16 splits (x, wq, wk, wv) and wo -> fp16
    {
        int tx = (MROWS * DIM) / 4;
        split_bf16<0><<<(tx + 255) / 256, 256>>>(x, pxs, tx);
        int tq = (NH * HD * DIM) / 4;
        split_bf16<1><<<(tq + 255) / 256, 256>>>(wq, pwqkvs, tq);
        int tk = (NKV * HD * DIM) / 4;
        split_bf16<1><<<(tk + 255) / 256, 256>>>(wk, pwqkvs + (size_t)(NH * HD) * KSPLIT, tk);
        split_bf16<1><<<(tk + 255) / 256, 256>>>(wv, pwqkvs + (size_t)(NH * HD + NKV * HD) * KSPLIT, tk);
        int to = (DIM * NH * HD) / 4;
        conv_fp16<<<(to + 255) / 256, 256>>>(wo, pwo16, to);
    }

    // 2) Fused QKV projection (bf16 3-term) + RoPE epilogue
    gemm_mma<1, 0><<<dim3(NQKV / 128, MROWS / 128), 256, GEMM_SMEM>>>(
        (const uint16_t*)pxs, (const uint16_t*)pwqkvs, nullptr, 0, KSPLIT, cosp, sinp);

    // 3) Sliding-window attention (writes fp16 attn output)
    attn_kernel<<<BB * NKV * (LL / 8), 512>>>();

    // 4) Output projection: fp16 single-term, K = 2048
    gemm_mma<0, 1><<<dim3(DIM / 128, MROWS / 128), 256, GEMM_SMEM>>>(
        (const uint16_t*)pao16, (const uint16_t*)pwo16, out, DIM, NH * HD, nullptr, nullptr);
}

// round 7
// speedup vs baseline: 4.0420x; 1.4990x over previous
#include <cuda_runtime.h>
#include <cuda_bf16.h>
#include <cuda_fp16.h>
#include <cstdint>

// ---------------------------------------------------------------------------
// Problem constants
// ---------------------------------------------------------------------------
#define BB 2
#define LL 2048
#define DIM 2048
#define NH 16
#define NKV 8
#define HD 128
#define WIN 128
#define NREP (NH / NKV)
#define MROWS (BB * LL)        // 4096
#define BK 32
#define NQKV (NH * HD + 2 * NKV * HD)   // 4096 fused QKV output cols

// ---------------------------------------------------------------------------
// Scratch (__device__ globals; no allocations allowed)
// ---------------------------------------------------------------------------
__device__ float g_q[(size_t)MROWS * NH * HD];
__device__ float g_k[(size_t)MROWS * NKV * HD];
__device__ float g_v[(size_t)MROWS * NKV * HD];

__device__ __half g_x16   [(size_t)MROWS * DIM];        // x, fp16
__device__ __half g_wqkv16[(size_t)NQKV * DIM];         // [wq;wk;wv], fp16
__device__ __half g_ao16  [(size_t)MROWS * (NH * HD)];  // attn out, fp16
__device__ __half g_wo16  [(size_t)DIM * (NH * HD)];    // wo, fp16

// ---------------------------------------------------------------------------
// PTX helpers (base sm_80+ PTX only — NO "a"-suffix features)
// ---------------------------------------------------------------------------
__device__ __forceinline__ uint32_t smem_u32(const void* p) {
    uint32_t a;
    asm("{ .reg .u64 t; cvta.to.shared.u64 t, %1; cvt.u32.u64 %0, t; }" : "=r"(a) : "l"(p));
    return a;
}
__device__ __forceinline__ void cp_async16(uint32_t dst, const void* src) {
    asm volatile("cp.async.cg.shared.global [%0], [%1], 16;"
                 :: "r"(dst), "l"(__cvta_generic_to_global(src)) : "memory");
}
__device__ __forceinline__ void cp_commit() {
    asm volatile("cp.async.commit_group;" ::: "memory");
}
template <int N>
__device__ __forceinline__ void cp_wait() {
    asm volatile("cp.async.wait_group %0;" :: "n"(N) : "memory");
}
__device__ __forceinline__ void ldsm4(uint32_t* r, uint32_t addr) {
    asm volatile("ldmatrix.sync.aligned.m8n8.x4.shared.b16 {%0,%1,%2,%3}, [%4];"
                 : "=r"(r[0]), "=r"(r[1]), "=r"(r[2]), "=r"(r[3]) : "r"(addr));
}
__device__ __forceinline__ void mma16816(float* d, const uint32_t* a, const uint32_t* b) {
    asm volatile(
        "mma.sync.aligned.m16n8k16.row.col.f32.f16.f16.f32 "
        "{%0,%1,%2,%3}, {%4,%5,%6,%7}, {%8,%9}, {%0,%1,%2,%3};"
        : "+f"(d[0]), "+f"(d[1]), "+f"(d[2]), "+f"(d[3])
        : "r"(a[0]), "r"(a[1]), "r"(a[2]), "r"(a[3]), "r"(b[0]), "r"(b[1]));
}

// ---------------------------------------------------------------------------
// HMMA GEMM (fp16 operands): C[m, n] = sum_k A[m,k] * B[n,k]
// CTA tile 128x128, BK=32, 5-stage cp.async pipeline, 8 warps (32x64 each).
// QKV=1: fused epilogue writes q/k/v with RoPE applied (smem-staged).
// QKV=0: plain fp32 store to C.
// ---------------------------------------------------------------------------
#define SROW 40                          // elems per smem row (32 data + 8 pad)
#define TILE_BYTES (128 * SROW * 2)      // 10240
#define STAGE_BYTES (2 * TILE_BYTES)     // A + B = 20480
#define STAGES 5
#define GEMM_SMEM (STAGES * STAGE_BYTES) // 102400

template <int QKV>
__global__ __launch_bounds__(256, 2)
void gemm_mma(const __half* __restrict__ Ag,
              const __half* __restrict__ Bg,
              float* __restrict__ C, int ldc, int kdim,
              const float* __restrict__ cosp, const float* __restrict__ sinp)
{
    extern __shared__ char smem_raw[];
    const uint32_t sb = smem_u32(smem_raw);
    const int t = threadIdx.x;
    const int lane = t & 31;
    const int wid = t >> 5;
    const int tile_m = blockIdx.y * 128;
    const int tile_n = blockIdx.x * 128;
    const int NTt = kdim / BK;

    const int wm = (wid & 3) * 32;   // warp row offset within tile
    const int wn = (wid >> 2) * 64;  // warp col offset within tile

    // ldmatrix per-thread byte offsets (within a stage)
    const int tsel = lane >> 3, r = lane & 7;
    uint32_t aoff[2], boff[4];
#pragma unroll
    for (int i = 0; i < 2; ++i)
        aoff[i] = ((wm + 16 * i + (tsel & 1) * 8 + r) * SROW + ((tsel & 2) ? 8 : 0)) * 2;
#pragma unroll
    for (int j = 0; j < 4; ++j)
        boff[j] = TILE_BYTES +
                  ((wn + 16 * j + ((tsel & 2) ? 8 : 0) + r) * SROW + ((tsel & 1) ? 8 : 0)) * 2;

    float acc[2][8][4];
#pragma unroll
    for (int mi = 0; mi < 2; ++mi)
#pragma unroll
        for (int ni = 0; ni < 8; ++ni)
#pragma unroll
            for (int e = 0; e < 4; ++e) acc[mi][ni][e] = 0.0f;

    auto load_stage = [&](int st, int kt) {
        uint32_t base = sb + st * STAGE_BYTES;
#pragma unroll
        for (int i = 0; i < 2; ++i) {
            int idx = t + i * 256;
            int row = idx >> 2, c = idx & 3;
            cp_async16(base + row * (SROW * 2) + c * 16,
                       Ag + (size_t)(tile_m + row) * kdim + kt * BK + c * 8);
            cp_async16(base + TILE_BYTES + row * (SROW * 2) + c * 16,
                       Bg + (size_t)(tile_n + row) * kdim + kt * BK + c * 8);
        }
    };

    // Prologue: fill 4 of 5 stages
#pragma unroll
    for (int s = 0; s < STAGES - 1; ++s) { load_stage(s, s); cp_commit(); }

    int cs_idx = 0, ld_idx = STAGES - 1;
    for (int kt = 0; kt < NTt; ++kt) {
        cp_wait<STAGES - 2>();
        __syncthreads();

        if (kt + STAGES - 1 < NTt) load_stage(ld_idx, kt + STAGES - 1);
        cp_commit();
        if (++ld_idx == STAGES) ld_idx = 0;

        uint32_t stb = sb + cs_idx * STAGE_BYTES;
        if (++cs_idx == STAGES) cs_idx = 0;
#pragma unroll
        for (int ks = 0; ks < 2; ++ks) {
            uint32_t a[2][4], b[4][4];
            ldsm4(a[0], stb + aoff[0] + ks * 32);
            ldsm4(a[1], stb + aoff[1] + ks * 32);
#pragma unroll
            for (int j = 0; j < 4; ++j) ldsm4(b[j], stb + boff[j] + ks * 32);
#pragma unroll
            for (int mi = 0; mi < 2; ++mi)
#pragma unroll
                for (int j = 0; j < 4; ++j) {
                    mma16816(acc[mi][2 * j],     a[mi], &b[j][0]);
                    mma16816(acc[mi][2 * j + 1], a[mi], &b[j][2]);
                }
        }
    }

    const int g = lane >> 2, c2 = (lane & 3) * 2;

    if (QKV) {
        // Stage C tile in smem, then apply RoPE (q,k) or copy (v)
        __syncthreads();
        float* cs = (float*)smem_raw;   // 128 x 132
#pragma unroll
        for (int mi = 0; mi < 2; ++mi)
#pragma unroll
            for (int ni = 0; ni < 8; ++ni) {
                int rr = wm + 16 * mi + g;
                int cc = wn + 8 * ni + c2;
                *(float2*)&cs[rr * 132 + cc]       = make_float2(acc[mi][ni][0], acc[mi][ni][1]);
                *(float2*)&cs[(rr + 8) * 132 + cc] = make_float2(acc[mi][ni][2], acc[mi][ni][3]);
            }
        __syncthreads();

        float* dst;
        int ldd, col0;
        bool rope;
        if (tile_n < NH * HD)                 { dst = g_q; ldd = NH * HD;  col0 = tile_n;                  rope = true;  }
        else if (tile_n < NH * HD + NKV * HD) { dst = g_k; ldd = NKV * HD; col0 = tile_n - NH * HD;        rope = true;  }
        else                                  { dst = g_v; ldd = NKV * HD; col0 = tile_n - NH*HD - NKV*HD; rope = false; }

        if (rope) {
            for (int it = t; it < 128 * 64; it += 256) {
                int rr = it >> 6, d = it & 63;
                int grow = tile_m + rr;
                int l = grow & (LL - 1);
                float t1 = cs[rr * 132 + d];
                float t2 = cs[rr * 132 + d + 64];
                float c1 = cosp[l * HD + d],       s1 = sinp[l * HD + d];
                float c2f = cosp[l * HD + d + 64], s2 = sinp[l * HD + d + 64];
                dst[(size_t)grow * ldd + col0 + d]      = t1 * c1 - t2 * s1;
                dst[(size_t)grow * ldd + col0 + d + 64] = t2 * c2f + t1 * s2;
            }
        } else {
            for (int it = t; it < 128 * 32; it += 256) {
                int rr = it >> 5, d = (it & 31) * 4;
                float4 v = *(float4*)&cs[rr * 132 + d];
                *(float4*)&dst[(size_t)(tile_m + rr) * ldd + col0 + d] = v;
            }
        }
    } else {
        // Plain fp32 store
#pragma unroll
        for (int mi = 0; mi < 2; ++mi) {
#pragma unroll
            for (int ni = 0; ni < 8; ++ni) {
                int row = tile_m + wm + 16 * mi + g;
                int col = tile_n + wn + 8 * ni + c2;
                *(float2*)(C + (size_t)row * ldc + col) =
                    make_float2(acc[mi][ni][0], acc[mi][ni][1]);
                *(float2*)(C + (size_t)(row + 8) * ldc + col) =
                    make_float2(acc[mi][ni][2], acc[mi][ni][3]);
            }
        }
    }
}

// ---------------------------------------------------------------------------
// fp32 -> fp16 convert, vectorized x4.
// ---------------------------------------------------------------------------
__global__ void conv_fp16(const float* __restrict__ src, __half* __restrict__ dst, int total4)
{
    int i = blockIdx.x * blockDim.x + threadIdx.x;
    if (i >= total4) return;
    float4 v = *(const float4*)(src + (size_t)i * 4);
    __half2 h0 = __floats2half2_rn(v.x, v.y);
    __half2 h1 = __floats2half2_rn(v.z, v.w);
    *(uint2*)(dst + (size_t)i * 4) = make_uint2(*(uint32_t*)&h0, *(uint32_t*)&h1);
}

// ---------------------------------------------------------------------------
// Sliding-window causal attention.
// 512 threads: 16 warps = 8 positions x 2 GQA heads sharing one KV head.
// Writes fp16 directly (feeds the fp16 O-projection).
// ---------------------------------------------------------------------------
__global__ __launch_bounds__(512)
void attn_kernel()
{
    const int lane = threadIdx.x & 31;
    const int w = threadIdx.x >> 5;       // 0..15
    const int bid = blockIdx.x;

    const int lt = bid % (LL / 8);
    const int bkh = bid / (LL / 8);
    const int kh = bkh % NKV;
    const int b = bkh / NKV;
    const int i = lt * 8 + (w >> 1);       // query position
    const int h = kh * NREP + (w & 1);     // query head
    const int KVD = NKV * HD;              // 1024

    __shared__ float sc[16][136];

    const float* qp = g_q + (((size_t)(b * LL + i)) * NH + h) * HD;
    float4 q = *(const float4*)(qp + 4 * lane);

    const int s = (i - WIN > 0) ? (i - WIN) : 0;
    const int cnt = i - s + 1;
    const float scale = 0.08838834764831845f;

    float mx = -1e30f;
    const float* kbase = g_k + ((size_t)(b * LL + s)) * KVD + kh * HD + 4 * lane;
    int j = 0;
    for (; j + 2 <= cnt; j += 2) {
        float4 k0 = *(const float4*)(kbase + (size_t)j * KVD);
        float4 k1 = *(const float4*)(kbase + (size_t)(j + 1) * KVD);
        float d0 = q.x * k0.x + q.y * k0.y + q.z * k0.z + q.w * k0.w;
        float d1 = q.x * k1.x + q.y * k1.y + q.z * k1.z + q.w * k1.w;
#pragma unroll
        for (int off = 16; off; off >>= 1) {
            d0 += __shfl_xor_sync(0xffffffffu, d0, off);
            d1 += __shfl_xor_sync(0xffffffffu, d1, off);
        }
        d0 *= scale; d1 *= scale;
        if (lane == 0) { sc[w][j] = d0; sc[w][j + 1] = d1; }
        mx = fmaxf(mx, fmaxf(d0, d1));
    }
    if (j < cnt) {
        float4 k0 = *(const float4*)(kbase + (size_t)j * KVD);
        float d0 = q.x * k0.x + q.y * k0.y + q.z * k0.z + q.w * k0.w;
#pragma unroll
        for (int off = 16; off; off >>= 1) d0 += __shfl_xor_sync(0xffffffffu, d0, off);
        d0 *= scale;
        if (lane == 0) sc[w][j] = d0;
        mx = fmaxf(mx, d0);
    }
    __syncwarp();

    float sum = 0.0f;
    for (int jj = lane; jj < cnt; jj += 32) {
        float e = __expf(sc[w][jj] - mx);
        sc[w][jj] = e;
        sum += e;
    }
#pragma unroll
    for (int off = 16; off; off >>= 1) sum += __shfl_xor_sync(0xffffffffu, sum, off);
    float inv = 1.0f / sum;
    __syncwarp();

    float ax = 0.f, ay = 0.f, az = 0.f, aw = 0.f;
    const float* vbase = g_v + ((size_t)(b * LL + s)) * KVD + kh * HD + 4 * lane;
    j = 0;
    for (; j + 2 <= cnt; j += 2) {
        float p0 = sc[w][j], p1 = sc[w][j + 1];
        float4 v0 = *(const float4*)(vbase + (size_t)j * KVD);
        float4 v1 = *(const float4*)(vbase + (size_t)(j + 1) * KVD);
        ax += p0 * v0.x + p1 * v1.x;
        ay += p0 * v0.y + p1 * v1.y;
        az += p0 * v0.z + p1 * v1.z;
        aw += p0 * v0.w + p1 * v1.w;
    }
    if (j < cnt) {
        float p0 = sc[w][j];
        float4 v0 = *(const float4*)(vbase + (size_t)j * KVD);
        ax += p0 * v0.x; ay += p0 * v0.y; az += p0 * v0.z; aw += p0 * v0.w;
    }

    __half* op = g_ao16 + ((size_t)(b * LL + i)) * (NH * HD) + h * HD + 4 * lane;
    __half2 o0 = __floats2half2_rn(ax * inv, ay * inv);
    __half2 o1 = __floats2half2_rn(az * inv, aw * inv);
    *(uint2*)op = make_uint2(*(uint32_t*)&o0, *(uint32_t*)&o1);
}

// ---------------------------------------------------------------------------
// Launcher
// ---------------------------------------------------------------------------
extern "C" void kernel_launch(void* const* d_in, const int* in_sizes, int n_in,
                              void* d_out, int out_size)
{
    const float* x    = (const float*)d_in[0];
    const float* cosp = (const float*)d_in[1];
    const float* sinp = (const float*)d_in[2];
    const float* wq   = (const float*)d_in[3];
    const float* wk   = (const float*)d_in[4];
    const float* wv   = (const float*)d_in[5];
    const float* wo   = (const float*)d_in[6];
    float* out = (float*)d_out;

    __half *px16, *pwqkv16, *pao16, *pwo16;
    cudaGetSymbolAddress((void**)&px16, g_x16);
    cudaGetSymbolAddress((void**)&pwqkv16, g_wqkv16);
    cudaGetSymbolAddress((void**)&pao16, g_ao16);
    cudaGetSymbolAddress((void**)&pwo16, g_wo16);

    cudaFuncSetAttribute((const void*)gemm_mma<1>, cudaFuncAttributeMaxDynamicSharedMemorySize, GEMM_SMEM);
    cudaFuncSetAttribute((const void*)gemm_mma<0>, cudaFuncAttributeMaxDynamicSharedMemorySize, GEMM_SMEM);

    // 1) fp32 -> fp16 conversions
    {
        int tx = (MROWS * DIM) / 4;
        conv_fp16<<<(tx + 255) / 256, 256>>>(x, px16, tx);
        int tq = (NH * HD * DIM) / 4;
        conv_fp16<<<(tq + 255) / 256, 256>>>(wq, pwqkv16, tq);
        int tk = (NKV * HD * DIM) / 4;
        conv_fp16<<<(tk + 255) / 256, 256>>>(wk, pwqkv16 + (size_t)(NH * HD) * DIM, tk);
        conv_fp16<<<(tk + 255) / 256, 256>>>(wv, pwqkv16 + (size_t)(NH * HD + NKV * HD) * DIM, tk);
        int to = (DIM * NH * HD) / 4;
        conv_fp16<<<(to + 255) / 256, 256>>>(wo, pwo16, to);
    }

    // 2) Fused QKV projection (fp16) + RoPE epilogue, K = 2048
    gemm_mma<1><<<dim3(NQKV / 128, MROWS / 128), 256, GEMM_SMEM>>>(
        px16, pwqkv16, nullptr, 0, DIM, cosp, sinp);

    // 3) Sliding-window attention (writes fp16 attn output)
    attn_kernel<<<BB * NKV * (LL / 8), 512>>>();

    // 4) Output projection: fp16, K = 2048
    gemm_mma<0><<<dim3(DIM / 128, MROWS / 128), 256, GEMM_SMEM>>>(
        pao16, pwo16, out, DIM, NH * HD, nullptr, nullptr);
}

// round 8
// speedup vs baseline: 7.3432x; 1.8167x over previous
#include <cuda_runtime.h>
#include <cuda_bf16.h>
#include <cuda_fp16.h>
#include <cstdint>

// ---------------------------------------------------------------------------
// Problem constants
// ---------------------------------------------------------------------------
#define BB 2
#define LL 2048
#define DIM 2048
#define NH 16
#define NKV 8
#define HD 128
#define WIN 128
#define NREP (NH / NKV)
#define MROWS (BB * LL)        // 4096
#define BK 32
#define NQKV (NH * HD + 2 * NKV * HD)   // 4096 fused QKV output cols

// ---------------------------------------------------------------------------
// Scratch (__device__ globals; no allocations allowed)
// ---------------------------------------------------------------------------
__device__ __half g_q16[(size_t)MROWS * NH * HD];
__device__ __half g_k16[(size_t)MROWS * NKV * HD];
__device__ __half g_v16[(size_t)MROWS * NKV * HD];

__device__ __half g_x16   [(size_t)MROWS * DIM];        // x, fp16
__device__ __half g_wqkv16[(size_t)NQKV * DIM];         // [wq;wk;wv], fp16
__device__ __half g_ao16  [(size_t)MROWS * (NH * HD)];  // attn out, fp16
__device__ __half g_wo16  [(size_t)DIM * (NH * HD)];    // wo, fp16

// ---------------------------------------------------------------------------
// PTX helpers (base sm_80+ PTX only — NO "a"-suffix features)
// ---------------------------------------------------------------------------
__device__ __forceinline__ uint32_t smem_u32(const void* p) {
    uint32_t a;
    asm("{ .reg .u64 t; cvta.to.shared.u64 t, %1; cvt.u32.u64 %0, t; }" : "=r"(a) : "l"(p));
    return a;
}
__device__ __forceinline__ void cp_async16(uint32_t dst, const void* src) {
    asm volatile("cp.async.cg.shared.global [%0], [%1], 16;"
                 :: "r"(dst), "l"(__cvta_generic_to_global(src)) : "memory");
}
__device__ __forceinline__ void cp_commit() {
    asm volatile("cp.async.commit_group;" ::: "memory");
}
template <int N>
__device__ __forceinline__ void cp_wait() {
    asm volatile("cp.async.wait_group %0;" :: "n"(N) : "memory");
}
__device__ __forceinline__ void ldsm4(uint32_t* r, uint32_t addr) {
    asm volatile("ldmatrix.sync.aligned.m8n8.x4.shared.b16 {%0,%1,%2,%3}, [%4];"
                 : "=r"(r[0]), "=r"(r[1]), "=r"(r[2]), "=r"(r[3]) : "r"(addr));
}
__device__ __forceinline__ void ldsm4t(uint32_t* r, uint32_t addr) {
    asm volatile("ldmatrix.sync.aligned.m8n8.x4.trans.shared.b16 {%0,%1,%2,%3}, [%4];"
                 : "=r"(r[0]), "=r"(r[1]), "=r"(r[2]), "=r"(r[3]) : "r"(addr));
}
__device__ __forceinline__ void mma16816(float* d, const uint32_t* a, const uint32_t* b) {
    asm volatile(
        "mma.sync.aligned.m16n8k16.row.col.f32.f16.f16.f32 "
        "{%0,%1,%2,%3}, {%4,%5,%6,%7}, {%8,%9}, {%0,%1,%2,%3};"
        : "+f"(d[0]), "+f"(d[1]), "+f"(d[2]), "+f"(d[3])
        : "r"(a[0]), "r"(a[1]), "r"(a[2]), "r"(a[3]), "r"(b[0]), "r"(b[1]));
}

// ---------------------------------------------------------------------------
// HMMA GEMM (fp16 operands): C[m, n] = sum_k A[m,k] * B[n,k]
// CTA tile 128x128, BK=32, 5-stage cp.async pipeline, 8 warps (32x64 each).
// QKV=1: fused epilogue writes q/k/v in fp16 with RoPE applied (smem-staged).
// QKV=0: plain fp32 store to C.
// ---------------------------------------------------------------------------
#define SROW 40                          // elems per smem row (32 data + 8 pad)
#define TILE_BYTES (128 * SROW * 2)      // 10240
#define STAGE_BYTES (2 * TILE_BYTES)     // A + B = 20480
#define STAGES 5
#define GEMM_SMEM (STAGES * STAGE_BYTES) // 102400

template <int QKV>
__global__ __launch_bounds__(256, 2)
void gemm_mma(const __half* __restrict__ Ag,
              const __half* __restrict__ Bg,
              float* __restrict__ C, int ldc, int kdim,
              const float* __restrict__ cosp, const float* __restrict__ sinp)
{
    extern __shared__ char smem_raw[];
    const uint32_t sb = smem_u32(smem_raw);
    const int t = threadIdx.x;
    const int lane = t & 31;
    const int wid = t >> 5;
    const int tile_m = blockIdx.y * 128;
    const int tile_n = blockIdx.x * 128;
    const int NTt = kdim / BK;

    const int wm = (wid & 3) * 32;
    const int wn = (wid >> 2) * 64;

    const int tsel = lane >> 3, r = lane & 7;
    uint32_t aoff[2], boff[4];
#pragma unroll
    for (int i = 0; i < 2; ++i)
        aoff[i] = ((wm + 16 * i + (tsel & 1) * 8 + r) * SROW + ((tsel & 2) ? 8 : 0)) * 2;
#pragma unroll
    for (int j = 0; j < 4; ++j)
        boff[j] = TILE_BYTES +
                  ((wn + 16 * j + ((tsel & 2) ? 8 : 0) + r) * SROW + ((tsel & 1) ? 8 : 0)) * 2;

    float acc[2][8][4];
#pragma unroll
    for (int mi = 0; mi < 2; ++mi)
#pragma unroll
        for (int ni = 0; ni < 8; ++ni)
#pragma unroll
            for (int e = 0; e < 4; ++e) acc[mi][ni][e] = 0.0f;

    auto load_stage = [&](int st, int kt) {
        uint32_t base = sb + st * STAGE_BYTES;
#pragma unroll
        for (int i = 0; i < 2; ++i) {
            int idx = t + i * 256;
            int row = idx >> 2, c = idx & 3;
            cp_async16(base + row * (SROW * 2) + c * 16,
                       Ag + (size_t)(tile_m + row) * kdim + kt * BK + c * 8);
            cp_async16(base + TILE_BYTES + row * (SROW * 2) + c * 16,
                       Bg + (size_t)(tile_n + row) * kdim + kt * BK + c * 8);
        }
    };

#pragma unroll
    for (int s = 0; s < STAGES - 1; ++s) { load_stage(s, s); cp_commit(); }

    int cs_idx = 0, ld_idx = STAGES - 1;
    for (int kt = 0; kt < NTt; ++kt) {
        cp_wait<STAGES - 2>();
        __syncthreads();

        if (kt + STAGES - 1 < NTt) load_stage(ld_idx, kt + STAGES - 1);
        cp_commit();
        if (++ld_idx == STAGES) ld_idx = 0;

        uint32_t stb = sb + cs_idx * STAGE_BYTES;
        if (++cs_idx == STAGES) cs_idx = 0;
#pragma unroll
        for (int ks = 0; ks < 2; ++ks) {
            uint32_t a[2][4], b[4][4];
            ldsm4(a[0], stb + aoff[0] + ks * 32);
            ldsm4(a[1], stb + aoff[1] + ks * 32);
#pragma unroll
            for (int j = 0; j < 4; ++j) ldsm4(b[j], stb + boff[j] + ks * 32);
#pragma unroll
            for (int mi = 0; mi < 2; ++mi)
#pragma unroll
                for (int j = 0; j < 4; ++j) {
                    mma16816(acc[mi][2 * j],     a[mi], &b[j][0]);
                    mma16816(acc[mi][2 * j + 1], a[mi], &b[j][2]);
                }
        }
    }

    const int g = lane >> 2, c2 = (lane & 3) * 2;

    if (QKV) {
        // Stage C tile in smem, then apply RoPE (q,k) or copy (v), store fp16
        __syncthreads();
        float* cs = (float*)smem_raw;   // 128 x 132
#pragma unroll
        for (int mi = 0; mi < 2; ++mi)
#pragma unroll
            for (int ni = 0; ni < 8; ++ni) {
                int rr = wm + 16 * mi + g;
                int cc = wn + 8 * ni + c2;
                *(float2*)&cs[rr * 132 + cc]       = make_float2(acc[mi][ni][0], acc[mi][ni][1]);
                *(float2*)&cs[(rr + 8) * 132 + cc] = make_float2(acc[mi][ni][2], acc[mi][ni][3]);
            }
        __syncthreads();

        __half* dst;
        int ldd, col0;
        bool rope;
        if (tile_n < NH * HD)                 { dst = g_q16; ldd = NH * HD;  col0 = tile_n;                  rope = true;  }
        else if (tile_n < NH * HD + NKV * HD) { dst = g_k16; ldd = NKV * HD; col0 = tile_n - NH * HD;        rope = true;  }
        else                                  { dst = g_v16; ldd = NKV * HD; col0 = tile_n - NH*HD - NKV*HD; rope = false; }

        if (rope) {
            for (int it = t; it < 128 * 64; it += 256) {
                int rr = it >> 6, d = it & 63;
                int grow = tile_m + rr;
                int l = grow & (LL - 1);
                float t1 = cs[rr * 132 + d];
                float t2 = cs[rr * 132 + d + 64];
                float c1 = cosp[l * HD + d],       s1 = sinp[l * HD + d];
                float c2f = cosp[l * HD + d + 64], s2 = sinp[l * HD + d + 64];
                dst[(size_t)grow * ldd + col0 + d]      = __float2half(t1 * c1 - t2 * s1);
                dst[(size_t)grow * ldd + col0 + d + 64] = __float2half(t2 * c2f + t1 * s2);
            }
        } else {
            for (int it = t; it < 128 * 32; it += 256) {
                int rr = it >> 5, d = (it & 31) * 4;
                float4 v = *(float4*)&cs[rr * 132 + d];
                __half2 h0 = __floats2half2_rn(v.x, v.y);
                __half2 h1 = __floats2half2_rn(v.z, v.w);
                *(uint2*)&dst[(size_t)(tile_m + rr) * ldd + col0 + d] =
                    make_uint2(*(uint32_t*)&h0, *(uint32_t*)&h1);
            }
        }
    } else {
#pragma unroll
        for (int mi = 0; mi < 2; ++mi) {
#pragma unroll
            for (int ni = 0; ni < 8; ++ni) {
                int row = tile_m + wm + 16 * mi + g;
                int col = tile_n + wn + 8 * ni + c2;
                *(float2*)(C + (size_t)row * ldc + col) =
                    make_float2(acc[mi][ni][0], acc[mi][ni][1]);
                *(float2*)(C + (size_t)(row + 8) * ldc + col) =
                    make_float2(acc[mi][ni][2], acc[mi][ni][3]);
            }
        }
    }
}

// ---------------------------------------------------------------------------
// fp32 -> fp16 convert, vectorized x4.
// ---------------------------------------------------------------------------
__global__ void conv_fp16(const float* __restrict__ src, __half* __restrict__ dst, int total4)
{
    int i = blockIdx.x * blockDim.x + threadIdx.x;
    if (i >= total4) return;
    float4 v = *(const float4*)(src + (size_t)i * 4);
    __half2 h0 = __floats2half2_rn(v.x, v.y);
    __half2 h1 = __floats2half2_rn(v.z, v.w);
    *(uint2*)(dst + (size_t)i * 4) = make_uint2(*(uint32_t*)&h0, *(uint32_t*)&h1);
}

// ---------------------------------------------------------------------------
// Tensor-core sliding-window attention.
// Block = 64 queries x 1 head; 4 warps (16 query rows each).
// Keys in 3 contiguous 64-key tiles [qt-128, qt+64). One-shot softmax.
// ---------------------------------------------------------------------------
#define ATS 136                 // fp16 elems per smem row (128 + 8 pad)
#define ATSZ (64 * ATS)         // elems per 64-row tile
#define ATT_SMEM (7 * ATSZ * 2) // Q + 3K + 3V = 121856 bytes

__global__ __launch_bounds__(128, 1)
void attn_mma_kernel()
{
    extern __shared__ __half smh[];
    const uint32_t sb = smem_u32(smh);
    const int t = threadIdx.x;
    const int lane = t & 31;
    const int w = t >> 5;
    const int qt = blockIdx.x * 64;
    const int h = blockIdx.y;
    const int b = blockIdx.z;
    const int kh = h >> 1;                 // NREP = 2
    const int tsel = lane >> 3, rr = lane & 7;
    const int kb0 = qt - 128;
    const int tfirst = (qt >= 128) ? 0 : ((qt >= 64) ? 1 : 2);

    // ---- async loads: group0 = {Q, K0, V0}, group1 = {K1, V1}, group2 = {K2, V2}
    {
        const __half* Qg = g_q16 + ((size_t)(b * LL + qt)) * (NH * HD) + h * HD;
#pragma unroll
        for (int i = 0; i < 8; ++i) {
            int ch = t + i * 128;
            int row = ch >> 4, c = ch & 15;
            cp_async16(sb + (row * ATS + c * 8) * 2, Qg + row * (NH * HD) + c * 8);
        }
    }
    auto ldKV = [&](int ti) {
        const __half* Kg = g_k16 + ((size_t)(b * LL + kb0 + ti * 64)) * (NKV * HD) + kh * HD;
        const __half* Vg = g_v16 + ((size_t)(b * LL + kb0 + ti * 64)) * (NKV * HD) + kh * HD;
        uint32_t kb = sb + (1 + ti) * (ATSZ * 2);
        uint32_t vb = sb + (4 + ti) * (ATSZ * 2);
#pragma unroll
        for (int i = 0; i < 8; ++i) {
            int ch = t + i * 128;
            int row = ch >> 4, c = ch & 15;
            cp_async16(kb + (row * ATS + c * 8) * 2, Kg + row * (NKV * HD) + c * 8);
            cp_async16(vb + (row * ATS + c * 8) * 2, Vg + row * (NKV * HD) + c * 8);
        }
    };
    if (tfirst <= 0) ldKV(0);
    cp_commit();
    if (tfirst <= 1) ldKV(1);
    cp_commit();
    ldKV(2);
    cp_commit();

    // ---- Q fragments (8 d-steps)
    cp_wait<2>();
    __syncthreads();
    uint32_t qf[8][4];
#pragma unroll
    for (int ds = 0; ds < 8; ++ds)
        ldsm4(qf[ds], sb + ((w * 16 + (tsel & 1) * 8 + rr) * ATS + ds * 16 + ((tsel & 2) ? 8 : 0)) * 2);

    // ---- S = Q K^T over 24 n8-blocks (192 keys)
    float S[24][4];
#pragma unroll
    for (int blk = 0; blk < 24; ++blk)
#pragma unroll
        for (int e = 0; e < 4; ++e) S[blk][e] = 0.0f;

    auto qk_tile = [&](int ti) {
        uint32_t kbase = sb + (1 + ti) * (ATSZ * 2);
#pragma unroll
        for (int jb = 0; jb < 4; ++jb) {
#pragma unroll
            for (int ds = 0; ds < 8; ++ds) {
                uint32_t kf[4];
                ldsm4(kf, kbase + ((jb * 16 + ((tsel & 2) ? 8 : 0) + rr) * ATS +
                                   ds * 16 + ((tsel & 1) ? 8 : 0)) * 2);
                mma16816(S[ti * 8 + 2 * jb],     qf[ds], &kf[0]);
                mma16816(S[ti * 8 + 2 * jb + 1], qf[ds], &kf[2]);
            }
        }
    };
    if (tfirst <= 0) qk_tile(0);
    cp_wait<1>();
    __syncthreads();
    if (tfirst <= 1) qk_tile(1);
    cp_wait<0>();
    __syncthreads();
    qk_tile(2);

    // ---- mask + softmax (register-resident)
    const float scale = 0.08838834764831845f;
    const int g = lane >> 2, doff = (lane & 3) * 2;
    const int qlo = qt + w * 16 + g;
    const int qhi = qlo + 8;

    float mxlo = -1e30f, mxhi = -1e30f;
#pragma unroll
    for (int blk = 0; blk < 24; ++blk) {
        int k0 = kb0 + blk * 8 + doff;
        int k1 = k0 + 1;
        S[blk][0] = (k0 >= 0 && k0 <= qlo && qlo - k0 <= WIN) ? S[blk][0] * scale : -1e30f;
        S[blk][1] = (k1 >= 0 && k1 <= qlo && qlo - k1 <= WIN) ? S[blk][1] * scale : -1e30f;
        S[blk][2] = (k0 >= 0 && k0 <= qhi && qhi - k0 <= WIN) ? S[blk][2] * scale : -1e30f;
        S[blk][3] = (k1 >= 0 && k1 <= qhi && qhi - k1 <= WIN) ? S[blk][3] * scale : -1e30f;
        mxlo = fmaxf(mxlo, fmaxf(S[blk][0], S[blk][1]));
        mxhi = fmaxf(mxhi, fmaxf(S[blk][2], S[blk][3]));
    }
    mxlo = fmaxf(mxlo, __shfl_xor_sync(0xffffffffu, mxlo, 1));
    mxlo = fmaxf(mxlo, __shfl_xor_sync(0xffffffffu, mxlo, 2));
    mxhi = fmaxf(mxhi, __shfl_xor_sync(0xffffffffu, mxhi, 1));
    mxhi = fmaxf(mxhi, __shfl_xor_sync(0xffffffffu, mxhi, 2));

    float smlo = 0.0f, smhi = 0.0f;
    uint32_t P[24][2];
#pragma unroll
    for (int blk = 0; blk < 24; ++blk) {
        float e0 = __expf(S[blk][0] - mxlo);
        float e1 = __expf(S[blk][1] - mxlo);
        float e2 = __expf(S[blk][2] - mxhi);
        float e3 = __expf(S[blk][3] - mxhi);
        smlo += e0 + e1;
        smhi += e2 + e3;
        __half2 plo = __floats2half2_rn(e0, e1);
        __half2 phi = __floats2half2_rn(e2, e3);
        P[blk][0] = *(uint32_t*)&plo;
        P[blk][1] = *(uint32_t*)&phi;
    }
    smlo += __shfl_xor_sync(0xffffffffu, smlo, 1);
    smlo += __shfl_xor_sync(0xffffffffu, smlo, 2);
    smhi += __shfl_xor_sync(0xffffffffu, smhi, 1);
    smhi += __shfl_xor_sync(0xffffffffu, smhi, 2);
    float invlo = 1.0f / smlo, invhi = 1.0f / smhi;

    // ---- O = P V
    float O[16][4];
#pragma unroll
    for (int nb = 0; nb < 16; ++nb)
#pragma unroll
        for (int e = 0; e < 4; ++e) O[nb][e] = 0.0f;

    const int ks0 = tfirst * 4;
#pragma unroll
    for (int nb = 0; nb < 8; ++nb) {
        for (int ks = ks0; ks < 12; ++ks) {
            int ti = ks >> 2;
            int krow = (ks & 3) * 16 + (tsel & 1) * 8 + rr;
            uint32_t vf[4];
            ldsm4t(vf, sb + (4 + ti) * (ATSZ * 2) +
                       (krow * ATS + nb * 16 + ((tsel & 2) ? 8 : 0)) * 2);
            uint32_t A[4] = {P[2 * ks][0], P[2 * ks][1], P[2 * ks + 1][0], P[2 * ks + 1][1]};
            mma16816(O[2 * nb],     A, &vf[0]);
            mma16816(O[2 * nb + 1], A, &vf[2]);
        }
    }

    // ---- normalize + store fp16
    __half* olo = g_ao16 + ((size_t)(b * LL + qlo)) * (NH * HD) + h * HD;
    __half* ohi = g_ao16 + ((size_t)(b * LL + qhi)) * (NH * HD) + h * HD;
#pragma unroll
    for (int nb = 0; nb < 16; ++nb) {
        int d = nb * 8 + doff;
        __half2 lo = __floats2half2_rn(O[nb][0] * invlo, O[nb][1] * invlo);
        __half2 hi = __floats2half2_rn(O[nb][2] * invhi, O[nb][3] * invhi);
        *(uint32_t*)&olo[d] = *(uint32_t*)&lo;
        *(uint32_t*)&ohi[d] = *(uint32_t*)&hi;
    }
}

// ---------------------------------------------------------------------------
// Launcher
// ---------------------------------------------------------------------------
extern "C" void kernel_launch(void* const* d_in, const int* in_sizes, int n_in,
                              void* d_out, int out_size)
{
    const float* x    = (const float*)d_in[0];
    const float* cosp = (const float*)d_in[1];
    const float* sinp = (const float*)d_in[2];
    const float* wq   = (const float*)d_in[3];
    const float* wk   = (const float*)d_in[4];
    const float* wv   = (const float*)d_in[5];
    const float* wo   = (const float*)d_in[6];
    float* out = (float*)d_out;

    __half *px16, *pwqkv16, *pao16, *pwo16;
    cudaGetSymbolAddress((void**)&px16, g_x16);
    cudaGetSymbolAddress((void**)&pwqkv16, g_wqkv16);
    cudaGetSymbolAddress((void**)&pao16, g_ao16);
    cudaGetSymbolAddress((void**)&pwo16, g_wo16);

    cudaFuncSetAttribute((const void*)gemm_mma<1>, cudaFuncAttributeMaxDynamicSharedMemorySize, GEMM_SMEM);
    cudaFuncSetAttribute((const void*)gemm_mma<0>, cudaFuncAttributeMaxDynamicSharedMemorySize, GEMM_SMEM);
    cudaFuncSetAttribute((const void*)attn_mma_kernel, cudaFuncAttributeMaxDynamicSharedMemorySize, ATT_SMEM);

    // 1) fp32 -> fp16 conversions
    {
        int tx = (MROWS * DIM) / 4;
        conv_fp16<<<(tx + 255) / 256, 256>>>(x, px16, tx);
        int tq = (NH * HD * DIM) / 4;
        conv_fp16<<<(tq + 255) / 256, 256>>>(wq, pwqkv16, tq);
        int tk = (NKV * HD * DIM) / 4;
        conv_fp16<<<(tk + 255) / 256, 256>>>(wk, pwqkv16 + (size_t)(NH * HD) * DIM, tk);
        conv_fp16<<<(tk + 255) / 256, 256>>>(wv, pwqkv16 + (size_t)(NH * HD + NKV * HD) * DIM, tk);
        int to = (DIM * NH * HD) / 4;
        conv_fp16<<<(to + 255) / 256, 256>>>(wo, pwo16, to);
    }

    // 2) Fused QKV projection (fp16) + RoPE epilogue -> fp16 q/k/v
    gemm_mma<1><<<dim3(NQKV / 128, MROWS / 128), 256, GEMM_SMEM>>>(
        px16, pwqkv16, nullptr, 0, DIM, cosp, sinp);

    // 3) Tensor-core sliding-window attention (fp16 in/out)
    attn_mma_kernel<<<dim3(LL / 64, NH, BB), 128, ATT_SMEM>>>();

    // 4) Output projection: fp16, K = 2048
    gemm_mma<0><<<dim3(DIM / 128, MROWS / 128), 256, GEMM_SMEM>>>(
        pao16, pwo16, out, DIM, NH * HD, nullptr, nullptr);
}